// round 6
// baseline (speedup 1.0000x reference)
#include <cuda_runtime.h>
#include <cuda_bf16.h>
#include <math.h>
#include <stdint.h>

#define NB 512
#define NT 128
#define NHE 512
#define NGE 2048
#define NZ 128
#define NHD 2048
#define NGD 8192
#define NOUTD 123
#define DATALD 129
#define DLD 133
#define HNBUF (NB * 2 * NHE)

#if !defined(__CUDA_ARCH__)
#define USE_TC 1
#elif defined(__CUDA_ARCH_FEAT_SM103_ALL) || defined(__CUDA_ARCH_FEAT_SM100_ALL)
#define USE_TC 1
#else
#define USE_TC 0
#endif

// ---------------- device scratch ----------------
__device__ __nv_bfloat16 g_dWhh_hi[NGD * NHD];
__device__ __nv_bfloat16 g_dWhh_lo[NGD * NHD];
__device__ __nv_bfloat16 g_eWf_hi[NGE * NHE];
__device__ __nv_bfloat16 g_eWf_lo[NGE * NHE];
__device__ __nv_bfloat16 g_eWb_hi[NGE * NHE];
__device__ __nv_bfloat16 g_eWb_lo[NGE * NHE];
__device__ __nv_bfloat16 g_eOut_hi[2 * NZ * 2 * NHE];
__device__ __nv_bfloat16 g_eOut_lo[2 * NZ * 2 * NHE];
__device__ __nv_bfloat16 g_initW_hi[2 * NHD * NZ];
__device__ __nv_bfloat16 g_initW_lo[2 * NHD * NZ];
__device__ __nv_bfloat16 g_zW_hi[NGD * NZ];
__device__ __nv_bfloat16 g_zW_lo[NGD * NZ];
__device__ __nv_bfloat16 g_outW_hi[NOUTD * NHD];
__device__ __nv_bfloat16 g_outW_lo[NOUTD * NHD];

__device__ float2 g_dWih2[NGD];        // permuted (x0,x1) weight pairs
__device__ float  g_db[NGD];           // permuted dec bias
__device__ float2 g_eWih2[2 * NGE];    // per dir
__device__ float  g_eb[2 * NGE];

__device__ __nv_bfloat16 g_hn_hi[2 * HNBUF];   // double-buffered encoder h
__device__ __nv_bfloat16 g_hn_lo[2 * HNBUF];
__device__ float g_ce[2 * NB * NHE];
__device__ float g_zml[NB * 2 * NZ];
__device__ __nv_bfloat16 g_z_hi[NB * NZ];
__device__ __nv_bfloat16 g_z_lo[NB * NZ];
__device__ float g_init[NB * 2 * NHD];
__device__ __nv_bfloat16 g_h0_hi[NB * NHD];
__device__ __nv_bfloat16 g_h0_lo[NB * NHD];
__device__ float g_cd[NB * NHD];
__device__ float g_zp[NB * NGD];
__device__ __nv_bfloat16 g_hs_hi[(size_t)NB * NT * NHD];
__device__ __nv_bfloat16 g_hs_lo[(size_t)NB * NT * NHD];

// ---------------- common helpers ----------------
__device__ __forceinline__ uint32_t smem_u32(const void* p) {
  uint32_t a;
  asm("{ .reg .u64 t; cvta.to.shared.u64 t, %1; cvt.u32.u64 %0, t; }" : "=r"(a) : "l"(p));
  return a;
}
__device__ __forceinline__ void cp16(uint32_t dst, const void* src, bool ok) {
  int sz = ok ? 16 : 0;
  asm volatile("cp.async.cg.shared.global [%0], [%1], 16, %2;\n"
               :: "r"(dst), "l"(src), "r"(sz) : "memory");
}
__device__ __forceinline__ void cp_commit() { asm volatile("cp.async.commit_group;" ::: "memory"); }
__device__ __forceinline__ void cp_wait1()  { asm volatile("cp.async.wait_group 1;" ::: "memory"); }
__device__ __forceinline__ void cp_wait0()  { asm volatile("cp.async.wait_group 0;" ::: "memory"); }

__device__ __forceinline__ float sigf(float x) { return 1.0f / (1.0f + expf(-x)); }
__device__ __forceinline__ void split_bf16(float x, __nv_bfloat16* hi, __nv_bfloat16* lo) {
  __nv_bfloat16 h = __float2bfloat16(x);
  *hi = h;
  *lo = __float2bfloat16(x - __bfloat162float(h));
}
// permuted row -> original gate-major row
__device__ __forceinline__ int orig_row(int np, int NH) {
  return ((np >> 3) & 3) * NH + ((np >> 5) << 3) + (np & 7);
}

struct GArg {
  const __nv_bfloat16 *Ahi = nullptr, *Alo = nullptr;  // [M][K], stride lda
  const __nv_bfloat16 *Whi = nullptr, *Wlo = nullptr;  // [N][K] packed
  const float *bias = nullptr;   // plain bias OR permuted enc bias
  const float *Cadd = nullptr;   // plain addend OR dec zp (stride ldc)
  float *C = nullptr;            // plain output
  const float2 *wih2 = nullptr;  // lstm: permuted input-weight pairs
  const float *data = nullptr;
  const int *lengths = nullptr;
  float *cstate = nullptr;       // lstm cell state base
  __nv_bfloat16 *ohi = nullptr, *olo = nullptr;  // lstm h out base
  long cstride = 0, ostride = 0;
  int mode = 0, t = 0, dir = 0;  // 0 plain, 1 enc-lstm, 2 dec-lstm
};

#define STAGE_BYTES 98304u
#define GSMEM (1024u + 2u * STAGE_BYTES)

#if USE_TC
// =====================================================================
// tcgen05 path
// =====================================================================
__device__ __forceinline__ uint32_t elect_one_pred() {
  uint32_t pred;
  asm volatile(
      "{\n\t.reg .pred p;\n\telect.sync _|p, 0xFFFFFFFF;\n\tselp.b32 %0, 1, 0, p;\n\t}"
      : "=r"(pred));
  return pred;
}
#define MBARRIER_INIT(addr, cnt) \
  asm volatile("mbarrier.init.shared.b64 [%0], %1;" :: "r"((uint32_t)(addr)), "r"((uint32_t)(cnt)) : "memory")
#define MBARRIER_WAIT_PARITY(addr, par) do {                                        \
  uint32_t _m = (uint32_t)(addr); uint32_t _p = (uint32_t)(par); uint32_t _d;       \
  asm volatile("{\n\t.reg .pred p;\n\t"                                             \
    "mbarrier.try_wait.parity.acquire.cta.shared::cta.b64 p, [%1], %2;\n\t"         \
    "selp.b32 %0, 1, 0, p;\n\t}" : "=r"(_d) : "r"(_m), "r"(_p) : "memory");         \
  if (!_d) {                                                                        \
    asm volatile("{\n\t.reg .pred P1;\n\t"                                          \
      "WL_%=:\n\t"                                                                  \
      "mbarrier.try_wait.parity.acquire.cta.shared::cta.b64 P1, [%0], %1, 0x989680;\n\t" \
      "@P1 bra.uni WD_%=;\n\t"                                                      \
      "bra.uni WL_%=;\n\t"                                                          \
      "WD_%=:\n\t}" :: "r"(_m), "r"(_p) : "memory");                                \
  }                                                                                 \
} while (0)

#define TCGEN05_ALLOC(sm, n) \
  asm volatile("tcgen05.alloc.cta_group::1.sync.aligned.shared::cta.b32 [%0], %1;" \
               :: "r"((uint32_t)(sm)), "r"((uint32_t)(n)) : "memory")
#define TCGEN05_DEALLOC(t, n) \
  asm volatile("tcgen05.dealloc.cta_group::1.sync.aligned.b32 %0, %1;" :: "r"(t), "r"((uint32_t)(n)))
#define TCGEN05_RELINQ() \
  asm volatile("tcgen05.relinquish_alloc_permit.cta_group::1.sync.aligned;")
#define TCGEN05_COMMIT(mb) \
  asm volatile("tcgen05.commit.cta_group::1.mbarrier::arrive::one.shared::cluster.b64 [%0];" \
               :: "r"((uint32_t)(mb)) : "memory")
#define TCGEN05_FENCE_AFTER()  asm volatile("tcgen05.fence::after_thread_sync;" ::: "memory")
#define TCGEN05_FENCE_BEFORE() asm volatile("tcgen05.fence::before_thread_sync;" ::: "memory")
#define TCGEN05_WAIT_LD()      asm volatile("tcgen05.wait::ld.sync.aligned;" ::: "memory")

#define TCGEN05_LD_32X32B_X32(r, addr)                                            \
  asm volatile(                                                                   \
      "tcgen05.ld.sync.aligned.32x32b.x32.b32 "                                   \
      "{%0, %1, %2, %3, %4, %5, %6, %7, %8, %9, %10, %11, %12, %13, %14, %15, "   \
      " %16, %17, %18, %19, %20, %21, %22, %23, %24, %25, %26, %27, %28, %29, %30, %31}, [%32];" \
      : "=r"((r)[0]), "=r"((r)[1]), "=r"((r)[2]), "=r"((r)[3]),                   \
        "=r"((r)[4]), "=r"((r)[5]), "=r"((r)[6]), "=r"((r)[7]),                   \
        "=r"((r)[8]), "=r"((r)[9]), "=r"((r)[10]), "=r"((r)[11]),                 \
        "=r"((r)[12]), "=r"((r)[13]), "=r"((r)[14]), "=r"((r)[15]),               \
        "=r"((r)[16]), "=r"((r)[17]), "=r"((r)[18]), "=r"((r)[19]),               \
        "=r"((r)[20]), "=r"((r)[21]), "=r"((r)[22]), "=r"((r)[23]),               \
        "=r"((r)[24]), "=r"((r)[25]), "=r"((r)[26]), "=r"((r)[27]),               \
        "=r"((r)[28]), "=r"((r)[29]), "=r"((r)[30]), "=r"((r)[31])                \
      : "r"(addr))

static constexpr unsigned long long SMEM_DESC_BASE_SW128 =
    (2ull << 61) | (1ull << 46) | (64ull << 32) | (1ull << 16);
#define MAKE_SMEM_DESC(a) (SMEM_DESC_BASE_SW128 | ((unsigned long long)((a) >> 4) & 0x3FFF))

static constexpr uint32_t IDESC =
    (1u << 4) | (1u << 7) | (1u << 10) | ((256u / 8u) << 17) | ((128u / 16u) << 24);

__device__ __forceinline__ void mma_ss(uint32_t d, unsigned long long a,
                                       unsigned long long b, uint32_t en) {
  asm volatile(
      "{\n\t.reg .pred p;\n\tsetp.ne.u32 p, %4, 0;\n\t"
      "tcgen05.mma.cta_group::1.kind::f16 [%0], %1, %2, %3, {%5, %5, %5, %5}, p;\n\t}"
      :: "r"(d), "l"(a), "l"(b), "r"(IDESC), "r"(en), "r"(0u) : "memory");
}

__device__ __forceinline__ void load_stage(
    uint32_t sb, int stage, int ci, const GArg& g, size_t lda,
    int m0, int n0, int N, int K, int tid)
{
  const uint32_t base = sb + 1024u + (uint32_t)stage * STAGE_BYTES;
  const int k0 = ci << 6;
#pragma unroll
  for (int it = 0; it < 4; ++it) {
    int idx = tid + (it << 8);
    int row = idx >> 3, c = idx & 7;
    uint32_t off = (uint32_t)((row << 7) + (c << 4));
    off ^= ((off >> 3) & 0x70);
    size_t so = (size_t)(m0 + row) * lda + (size_t)k0 + (c << 3);
    cp16(base + off, g.Ahi + so, true);
    cp16(base + 16384u + off, g.Alo + so, true);
  }
#pragma unroll
  for (int it = 0; it < 8; ++it) {
    int idx = tid + (it << 8);
    int row = idx >> 3, c = idx & 7;
    int n = n0 + row;
    bool ok = (n < N);
    size_t so = (size_t)(ok ? n : 0) * (size_t)K + (size_t)k0 + (c << 3);
    uint32_t off = (uint32_t)((row << 7) + (c << 4));
    off ^= ((off >> 3) & 0x70);
    cp16(base + 32768u + off, g.Whi + so, ok);
    cp16(base + 65536u + off, g.Wlo + so, ok);
  }
  cp_commit();
}

__device__ __forceinline__ void mma_chunk(uint32_t sb, int stage, uint32_t tmem, bool first) {
  uint32_t base = sb + 1024u + (uint32_t)stage * STAGE_BYTES;
  unsigned long long dAh = MAKE_SMEM_DESC(base);
  unsigned long long dAl = MAKE_SMEM_DESC(base + 16384u);
  unsigned long long dBh = MAKE_SMEM_DESC(base + 32768u);
  unsigned long long dBl = MAKE_SMEM_DESC(base + 65536u);
#pragma unroll
  for (int ks = 0; ks < 4; ++ks) {
    unsigned long long o = (unsigned long long)(2 * ks);
    mma_ss(tmem, dAh + o, dBh + o, (first && ks == 0) ? 0u : 1u);
    mma_ss(tmem, dAh + o, dBl + o, 1u);
    mma_ss(tmem, dAl + o, dBh + o, 1u);
  }
}

__global__ void __launch_bounds__(256, 1) gemm3(GArg a0, GArg a1, size_t lda,
                                                size_t ldc, int N, int K) {
  extern __shared__ __align__(1024) char smem[];
  const int tid = threadIdx.x;
  const uint32_t sb = smem_u32(smem);
  const GArg g = blockIdx.z ? a1 : a0;
  const int m0 = blockIdx.y * 128;
  const int n0 = blockIdx.x * 256;

  if (tid == 0) { MBARRIER_INIT(sb + 16, 1); MBARRIER_INIT(sb + 24, 1); }
  if (tid < 32) TCGEN05_ALLOC(sb, 256);
  __syncthreads();
  uint32_t tmem;
  asm volatile("ld.shared.b32 %0, [%1];" : "=r"(tmem) : "r"(sb));

  const int nch = K >> 6;
  load_stage(sb, 0, 0, g, lda, m0, n0, N, K, tid);
  load_stage(sb, 1, 1, g, lda, m0, n0, N, K, tid);

  for (int i = 0; i < nch; ++i) {
    const int b = i & 1;
    if (i + 1 < nch) cp_wait1(); else cp_wait0();
    asm volatile("fence.proxy.async.shared::cta;" ::: "memory");
    __syncthreads();
    if (tid < 32) {
      if (elect_one_pred()) {
        mma_chunk(sb, b, tmem, i == 0);
        TCGEN05_COMMIT(sb + 16 + 8 * b);
      }
    }
    if (i + 2 < nch) {
      MBARRIER_WAIT_PARITY(sb + 16 + 8 * b, (i >> 1) & 1);
      load_stage(sb, b, i + 2, g, lda, m0, n0, N, K, tid);
    }
  }
  const int last = nch - 1;
  MBARRIER_WAIT_PARITY(sb + 16 + 8 * (last & 1), (last >> 1) & 1);
  TCGEN05_FENCE_AFTER();

  const int wq = (tid >> 5) & 3, wg = tid >> 7, lane = tid & 31;
  const int b = m0 + wq * 32 + lane;

  if (g.mode == 0) {
    float* crow = g.C + (size_t)b * ldc;
    const float* arow = g.Cadd ? (g.Cadd + (size_t)b * ldc) : (const float*)0;
    for (int c0 = wg * 128; c0 < wg * 128 + 128; c0 += 32) {
      int n = n0 + c0;
      if (n >= N) break;
      uint32_t r[32];
      TCGEN05_LD_32X32B_X32(r, tmem + c0);
      TCGEN05_WAIT_LD();
      if (((ldc & 3) == 0) && (n + 32 <= N)) {
#pragma unroll
        for (int q = 0; q < 8; ++q) {
          float4 v;
          v.x = __uint_as_float(r[4 * q + 0]);
          v.y = __uint_as_float(r[4 * q + 1]);
          v.z = __uint_as_float(r[4 * q + 2]);
          v.w = __uint_as_float(r[4 * q + 3]);
          if (g.bias) {
            float4 bv = *(const float4*)(g.bias + n + 4 * q);
            v.x += bv.x; v.y += bv.y; v.z += bv.z; v.w += bv.w;
          }
          if (arow) {
            float4 av = *(const float4*)(arow + n + 4 * q);
            v.x += av.x; v.y += av.y; v.z += av.z; v.w += av.w;
          }
          *(float4*)(crow + n + 4 * q) = v;
        }
      } else {
        for (int j = 0; j < 32 && n + j < N; ++j) {
          float v = __uint_as_float(r[j]);
          if (g.bias) v += g.bias[n + j];
          if (arow) v += arow[n + j];
          crow[n + j] = v;
        }
      }
    }
  } else {
    // fused LSTM epilogue
    float x0, x1; int wok = 1;
    if (g.mode == 1) {
      int L = g.lengths[b]; L = L < 1 ? 1 : (L > NT ? NT : L);
      if (g.t >= L) wok = 0;
      int ti = g.dir ? (L - 1 - g.t) : g.t;
      x0 = g.data[((size_t)b * DATALD + ti + 1) * 2 + 0];
      x1 = g.data[((size_t)b * DATALD + ti + 1) * 2 + 1];
    } else {
      x0 = g.data[((size_t)b * DATALD + g.t) * 2 + 0];
      x1 = g.data[((size_t)b * DATALD + g.t) * 2 + 1];
    }
    const float* zrow = g.Cadd ? (g.Cadd + (size_t)b * ldc) : (const float*)0;
    for (int c0 = wg * 128; c0 < wg * 128 + 128; c0 += 32) {
      uint32_t r[32];
      TCGEN05_LD_32X32B_X32(r, tmem + c0);
      TCGEN05_WAIT_LD();
      const int ng = n0 + c0;
      const int jb = (ng >> 5) << 3;
#pragma unroll
      for (int u = 0; u < 8; ++u) {
        float pi = __uint_as_float(r[u]);
        float pf = __uint_as_float(r[8 + u]);
        float pg = __uint_as_float(r[16 + u]);
        float po = __uint_as_float(r[24 + u]);
        float2 wi = g.wih2[ng + u], wf = g.wih2[ng + 8 + u];
        float2 wgg = g.wih2[ng + 16 + u], wo = g.wih2[ng + 24 + u];
        pi += x0 * wi.x + x1 * wi.y;
        pf += x0 * wf.x + x1 * wf.y;
        pg += x0 * wgg.x + x1 * wgg.y;
        po += x0 * wo.x + x1 * wo.y;
        if (g.mode == 1) {
          pi += g.bias[ng + u]; pf += g.bias[ng + 8 + u];
          pg += g.bias[ng + 16 + u]; po += g.bias[ng + 24 + u];
        } else {
          pi += zrow[ng + u]; pf += zrow[ng + 8 + u];
          pg += zrow[ng + 16 + u]; po += zrow[ng + 24 + u];
        }
        int j = jb + u;
        size_t ci = (size_t)b * g.cstride + j;
        size_t oi = (size_t)b * g.ostride + j;
        if (wok) {
          float c2 = sigf(pf) * g.cstate[ci] + sigf(pi) * tanhf(pg);
          float h2 = sigf(po) * tanhf(c2);
          g.cstate[ci] = c2;
          split_bf16(h2, &g.ohi[oi], &g.olo[oi]);
        } else {
          g.ohi[oi] = g.Ahi[(size_t)b * lda + j];
          g.olo[oi] = g.Alo[(size_t)b * lda + j];
        }
      }
    }
  }
  TCGEN05_FENCE_BEFORE();
  __syncthreads();
  if (tid < 32) { TCGEN05_RELINQ(); TCGEN05_DEALLOC(tmem, 256); }
}

#else
// =====================================================================
// Fallback: mma.sync m16n8k16 bf16 + ldmatrix. Same modes.
// =====================================================================
#define KC 64
#define FSTAGE 65536u

__device__ __forceinline__ void ldsm4(uint32_t& r0, uint32_t& r1, uint32_t& r2,
                                      uint32_t& r3, uint32_t addr) {
  asm volatile("ldmatrix.sync.aligned.m8n8.x4.shared.b16 {%0,%1,%2,%3}, [%4];"
               : "=r"(r0), "=r"(r1), "=r"(r2), "=r"(r3) : "r"(addr));
}
__device__ __forceinline__ void mma16816(float* c, uint32_t a0, uint32_t a1,
                                         uint32_t a2, uint32_t a3,
                                         uint32_t b0, uint32_t b1) {
  asm volatile(
      "mma.sync.aligned.m16n8k16.row.col.f32.bf16.bf16.f32 "
      "{%0,%1,%2,%3}, {%4,%5,%6,%7}, {%8,%9}, {%0,%1,%2,%3};"
      : "+f"(c[0]), "+f"(c[1]), "+f"(c[2]), "+f"(c[3])
      : "r"(a0), "r"(a1), "r"(a2), "r"(a3), "r"(b0), "r"(b1));
}

__device__ __forceinline__ void f_load_stage(
    uint32_t sb, int stage, int ci, int hf, const GArg& g, size_t lda,
    int m0, int n0, int N, int K, int tid)
{
  const uint32_t base = sb + (uint32_t)stage * FSTAGE;
  const int k0 = ci * KC;
#pragma unroll
  for (int it = 0; it < 4; ++it) {
    int idx = tid + (it << 8);
    int row = idx >> 3, c = idx & 7;
    uint32_t off = (uint32_t)((row << 7) + (c << 4));
    off ^= (off >> 3) & 0x70;
    size_t soA = (size_t)(m0 + row) * lda + (size_t)k0 + (c << 3);
    cp16(base + off, g.Ahi + soA, true);
    cp16(base + 16384u + off, g.Alo + soA, true);
    int n = n0 + hf * 128 + row;
    bool ok = (n < N);
    size_t soB = (size_t)(ok ? n : 0) * (size_t)K + (size_t)k0 + (c << 3);
    cp16(base + 32768u + off, g.Whi + soB, ok);
    cp16(base + 49152u + off, g.Wlo + soB, ok);
  }
  cp_commit();
}

__global__ void __launch_bounds__(256, 1) gemm3(GArg a0, GArg a1, size_t lda,
                                                size_t ldc, int N, int K) {
  extern __shared__ __align__(1024) char smem[];
  const int tid = threadIdx.x;
  const uint32_t sb = smem_u32(smem);
  const GArg g = blockIdx.z ? a1 : a0;
  const int m0 = blockIdx.y * 128;
  const int n0 = blockIdx.x * 256;
  const int w = tid >> 5, l = tid & 31;
  const int r = l >> 2, c2 = (l & 3) << 1;
  const int nch = K / KC;

  const uint32_t l7 = (uint32_t)(l & 7);
  const uint32_t xm = l7 << 4;
  const uint32_t a_rowb = (uint32_t)((w * 16 + (l & 15)) << 7);
  const uint32_t a_kh = (uint32_t)((l >> 4) << 4);
  const uint32_t b_rowb = (uint32_t)((((l >> 4) << 3) + (int)l7) << 7);
  const uint32_t b_kh = (uint32_t)(((l >> 3) & 1) << 4);

  for (int hf = 0; hf < 2; ++hf) {
    if (n0 + hf * 128 >= N) break;
    float acc[16][4];
#pragma unroll
    for (int i = 0; i < 16; ++i)
#pragma unroll
      for (int j = 0; j < 4; ++j) acc[i][j] = 0.0f;

    f_load_stage(sb, 0, 0, hf, g, lda, m0, n0, N, K, tid);
    f_load_stage(sb, 1, 1, hf, g, lda, m0, n0, N, K, tid);

    for (int ci = 0; ci < nch; ++ci) {
      const int b = ci & 1;
      if (ci + 1 < nch) cp_wait1(); else cp_wait0();
      __syncthreads();
      const uint32_t Ah = sb + (uint32_t)b * FSTAGE;
      const uint32_t Al = Ah + 16384u;
      const uint32_t Bh = Ah + 32768u;
      const uint32_t Bl = Ah + 49152u;
#pragma unroll
      for (int ks = 0; ks < 4; ++ks) {
        const uint32_t akOff = (((uint32_t)(32 * ks) + a_kh) ^ xm);
        const uint32_t bkOff = (((uint32_t)(32 * ks) + b_kh) ^ xm);
        uint32_t ah0, ah1, ah2, ah3, al0, al1, al2, al3;
        ldsm4(ah0, ah1, ah2, ah3, Ah + a_rowb + akOff);
        ldsm4(al0, al1, al2, al3, Al + a_rowb + akOff);
#pragma unroll
        for (int np = 0; np < 8; ++np) {
          const uint32_t baddr = b_rowb + (uint32_t)(np << 11) + bkOff;
          uint32_t bh0, bh1, bh2, bh3, bl0, bl1, bl2, bl3;
          ldsm4(bh0, bh1, bh2, bh3, Bh + baddr);
          ldsm4(bl0, bl1, bl2, bl3, Bl + baddr);
          mma16816(acc[2 * np],     ah0, ah1, ah2, ah3, bh0, bh1);
          mma16816(acc[2 * np],     ah0, ah1, ah2, ah3, bl0, bl1);
          mma16816(acc[2 * np],     al0, al1, al2, al3, bh0, bh1);
          mma16816(acc[2 * np + 1], ah0, ah1, ah2, ah3, bh2, bh3);
          mma16816(acc[2 * np + 1], ah0, ah1, ah2, ah3, bl2, bl3);
          mma16816(acc[2 * np + 1], al0, al1, al2, al3, bh2, bh3);
        }
      }
      __syncthreads();
      if (ci + 2 < nch) f_load_stage(sb, b, ci + 2, hf, g, lda, m0, n0, N, K, tid);
    }

    const int mtop = m0 + w * 16 + r;
    if (g.mode == 0) {
#pragma unroll
      for (int nb = 0; nb < 16; ++nb) {
        int n = n0 + hf * 128 + nb * 8 + c2;
#pragma unroll
        for (int half = 0; half < 2; ++half) {
          int m = mtop + half * 8;
          float v0 = acc[nb][2 * half], v1 = acc[nb][2 * half + 1];
          if (g.bias) { v0 += g.bias[n < N ? n : 0]; v1 += (n + 1 < N) ? g.bias[n + 1] : 0.0f; }
          if (g.Cadd) {
            const float* arow = g.Cadd + (size_t)m * ldc;
            if (n < N) v0 += arow[n];
            if (n + 1 < N) v1 += arow[n + 1];
          }
          float* crow = g.C + (size_t)m * ldc;
          if (n < N) crow[n] = v0;
          if (n + 1 < N) crow[n + 1] = v1;
        }
      }
    } else {
#pragma unroll
      for (int half = 0; half < 2; ++half) {
        int m = mtop + half * 8;
        float x0, x1; int wok = 1;
        if (g.mode == 1) {
          int L = g.lengths[m]; L = L < 1 ? 1 : (L > NT ? NT : L);
          if (g.t >= L) wok = 0;
          int ti = g.dir ? (L - 1 - g.t) : g.t;
          x0 = g.data[((size_t)m * DATALD + ti + 1) * 2 + 0];
          x1 = g.data[((size_t)m * DATALD + ti + 1) * 2 + 1];
        } else {
          x0 = g.data[((size_t)m * DATALD + g.t) * 2 + 0];
          x1 = g.data[((size_t)m * DATALD + g.t) * 2 + 1];
        }
        const float* zrow = g.Cadd ? (g.Cadd + (size_t)m * ldc) : (const float*)0;
#pragma unroll
        for (int bb = 0; bb < 4; ++bb) {
          int nbase = n0 + hf * 128 + bb * 32;
          int jb = (nbase >> 5) << 3;
#pragma unroll
          for (int s = 0; s < 2; ++s) {   // column slot c2, c2+1
            int cc = c2 + s;
            int j = jb + cc;
            float pi = acc[4 * bb + 0][2 * half + s];
            float pf = acc[4 * bb + 1][2 * half + s];
            float pg = acc[4 * bb + 2][2 * half + s];
            float po = acc[4 * bb + 3][2 * half + s];
            float2 wi = g.wih2[nbase + cc], wf = g.wih2[nbase + 8 + cc];
            float2 wgg = g.wih2[nbase + 16 + cc], wo = g.wih2[nbase + 24 + cc];
            pi += x0 * wi.x + x1 * wi.y;
            pf += x0 * wf.x + x1 * wf.y;
            pg += x0 * wgg.x + x1 * wgg.y;
            po += x0 * wo.x + x1 * wo.y;
            if (g.mode == 1) {
              pi += g.bias[nbase + cc]; pf += g.bias[nbase + 8 + cc];
              pg += g.bias[nbase + 16 + cc]; po += g.bias[nbase + 24 + cc];
            } else {
              pi += zrow[nbase + cc]; pf += zrow[nbase + 8 + cc];
              pg += zrow[nbase + 16 + cc]; po += zrow[nbase + 24 + cc];
            }
            size_t cidx = (size_t)m * g.cstride + j;
            size_t oidx = (size_t)m * g.ostride + j;
            if (wok) {
              float cv = sigf(pf) * g.cstate[cidx] + sigf(pi) * tanhf(pg);
              float hv = sigf(po) * tanhf(cv);
              g.cstate[cidx] = cv;
              split_bf16(hv, &g.ohi[oidx], &g.olo[oidx]);
            } else {
              g.ohi[oidx] = g.Ahi[(size_t)m * lda + j];
              g.olo[oidx] = g.Alo[(size_t)m * lda + j];
            }
          }
        }
      }
    }
  }
}
#endif  // USE_TC

// ---------------- cvt_all: weight split/permute + state init ----------------
#define L0 16777216L
#define L1 (L0 + 1048576L)
#define L2 (L1 + 1048576L)
#define L3 (L2 + 262144L)
#define L4 (L3 + 524288L)
#define L5 (L4 + 1048576L)
#define L6 (L5 + 251904L)
#define L7 (L6 + 1048576L)
#define L8 (L7 + 8192L)
#define L9 (L8 + 4096L)
__global__ void cvt_all(const float* __restrict__ dWhh, const float* __restrict__ eWf,
                        const float* __restrict__ eWb, const float* __restrict__ eOut,
                        const float* __restrict__ initW, const float* __restrict__ decWih,
                        const float* __restrict__ outW, const float* __restrict__ decB,
                        const float* __restrict__ encBf, const float* __restrict__ encBb) {
  long idx = blockIdx.x * 256L + threadIdx.x;
  if (idx >= L9) return;
  if (idx < L0) {                       // decoder Whh, permuted rows
    long row = idx >> 11, k = idx & 2047;
    split_bf16(dWhh[(long)orig_row((int)row, NHD) * NHD + k], &g_dWhh_hi[idx], &g_dWhh_lo[idx]);
  } else if (idx < L1) {                // enc fwd Whh
    long i = idx - L0, row = i >> 9, k = i & 511;
    split_bf16(eWf[(long)orig_row((int)row, NHE) * NHE + k], &g_eWf_hi[i], &g_eWf_lo[i]);
  } else if (idx < L2) {                // enc bwd Whh
    long i = idx - L1, row = i >> 9, k = i & 511;
    split_bf16(eWb[(long)orig_row((int)row, NHE) * NHE + k], &g_eWb_hi[i], &g_eWb_lo[i]);
  } else if (idx < L3) {
    long i = idx - L2; split_bf16(eOut[i], &g_eOut_hi[i], &g_eOut_lo[i]);
  } else if (idx < L4) {
    long i = idx - L3; split_bf16(initW[i], &g_initW_hi[i], &g_initW_lo[i]);
  } else if (idx < L5) {                // zW permuted
    long i = idx - L4, row = i >> 7, k = i & 127;
    split_bf16(decWih[(long)orig_row((int)row, NHD) * DLD + 5 + k], &g_zW_hi[i], &g_zW_lo[i]);
  } else if (idx < L6) {
    long i = idx - L5; split_bf16(outW[i], &g_outW_hi[i], &g_outW_lo[i]);
  } else if (idx < L7) {                // zero hn (both bufs) + ce
    long i = idx - L6;
    g_hn_hi[i] = __float2bfloat16(0.0f);
    g_hn_lo[i] = __float2bfloat16(0.0f);
    if (i < 2 * NB * NHE) g_ce[i] = 0.0f;
  } else if (idx < L8) {                // dec Wih pairs + bias, permuted
    int np = (int)(idx - L7);
    int o = orig_row(np, NHD);
    g_dWih2[np] = make_float2(decWih[(long)o * DLD], decWih[(long)o * DLD + 1]);
    g_db[np] = decB[o];
  } else {                              // enc Wih pairs + bias, permuted, per dir
    int i = (int)(idx - L8);
    int dir = i >> 11, np = i & 2047;
    int o = orig_row(np, NHE);
    const float* W = dir ? eWb : eWf;   // placeholder; real enc Wih passed below
    (void)W;
    const float* Wih = dir ? encBb : encBf;  // not used; see below
    (void)Wih;
    // enc Wih pairs come from enc_Wih_{f,b} which we pass via decB slots? ->
    // handled by second kernel below (kept simple); here only bias:
    g_eb[i] = (dir ? encBb : encBf)[o];
  }
}
// enc Wih pairs (tiny) — separate kernel to keep cvt_all arg count sane
__global__ void cvt_encwih(const float* __restrict__ Wf, const float* __restrict__ Wb) {
  int i = blockIdx.x * 256 + threadIdx.x;    // 2*2048
  if (i >= 2 * NGE) return;
  int dir = i >> 11, np = i & 2047;
  int o = orig_row(np, NHE);
  const float* W = dir ? Wb : Wf;
  g_eWih2[i] = make_float2(W[2 * o], W[2 * o + 1]);
}

// ---------------- small kernels ----------------
__global__ void latent_kernel(const float* __restrict__ eps,
                              float* __restrict__ zm_out,
                              float* __restrict__ zl_out) {
  int idx = blockIdx.x * blockDim.x + threadIdx.x;
  int b = idx >> 7, k = idx & 127;
  float zm = g_zml[b * 256 + k];
  float zl = g_zml[b * 256 + 128 + k];
  zm_out[idx] = zm;
  zl_out[idx] = zl;
  float z = zm + expf(0.5f * zl) * eps[idx];
  split_bf16(z, &g_z_hi[idx], &g_z_lo[idx]);
}

__global__ void initsplit_kernel() {
  int idx = blockIdx.x * blockDim.x + threadIdx.x;
  int b = idx >> 11, j = idx & 2047;
  float h0 = tanhf(g_init[b * (2 * NHD) + j]);
  float c0 = tanhf(g_init[b * (2 * NHD) + NHD + j]);
  g_cd[idx] = c0;
  split_bf16(h0, &g_h0_hi[idx], &g_h0_lo[idx]);
}

// ---------------- launch ----------------
static inline void run_gemm(const GArg& a0, const GArg& a1, size_t lda, size_t ldc,
                            int N, int K, int M, int nz) {
  dim3 grid((unsigned)((N + 255) / 256), (unsigned)(M / 128), (unsigned)nz);
  gemm3<<<grid, 256, GSMEM>>>(a0, a1, lda, ldc, N, K);
}

extern "C" void kernel_launch(void* const* d_in, const int* in_sizes, int n_in,
                              void* d_out, int out_size) {
  const float* data      = (const float*)d_in[0];
  const float* eps       = (const float*)d_in[1];
  const float* enc_Wih_f = (const float*)d_in[2];
  const float* enc_Whh_f = (const float*)d_in[3];
  const float* enc_b_f   = (const float*)d_in[4];
  const float* enc_Wih_b = (const float*)d_in[5];
  const float* enc_Whh_b = (const float*)d_in[6];
  const float* enc_b_b   = (const float*)d_in[7];
  const float* enc_out_W = (const float*)d_in[8];
  const float* enc_out_b = (const float*)d_in[9];
  const float* init_W    = (const float*)d_in[10];
  const float* init_b    = (const float*)d_in[11];
  const float* dec_Wih   = (const float*)d_in[12];
  const float* dec_Whh   = (const float*)d_in[13];
  const float* dec_b     = (const float*)d_in[14];
  const float* out_W     = (const float*)d_in[15];
  const float* out_b     = (const float*)d_in[16];
  const int*   lengths   = (const int*)d_in[17];

  float* out    = (float*)d_out;
  float* params = out;
  float* zm_out = out + (size_t)NB * NT * NOUTD;
  float* zl_out = zm_out + (size_t)NB * NT;

  cudaFuncSetAttribute(gemm3, cudaFuncAttributeMaxDynamicSharedMemorySize, GSMEM);

#define SYM(p, s) cudaGetSymbolAddress((void**)&p, s)
  __nv_bfloat16 *dWhh_hi, *dWhh_lo, *eWf_hi, *eWf_lo, *eWb_hi, *eWb_lo;
  __nv_bfloat16 *eOut_hi, *eOut_lo, *initW_hi, *initW_lo, *zW_hi, *zW_lo, *outW_hi, *outW_lo;
  __nv_bfloat16 *hn_hi, *hn_lo, *z_hi, *z_lo, *h0_hi, *h0_lo, *hs_hi, *hs_lo;
  float *ce, *zml, *initb, *zp, *cd, *db, *eb;
  float2 *dWih2, *eWih2;
  SYM(dWhh_hi, g_dWhh_hi); SYM(dWhh_lo, g_dWhh_lo);
  SYM(eWf_hi, g_eWf_hi); SYM(eWf_lo, g_eWf_lo);
  SYM(eWb_hi, g_eWb_hi); SYM(eWb_lo, g_eWb_lo);
  SYM(eOut_hi, g_eOut_hi); SYM(eOut_lo, g_eOut_lo);
  SYM(initW_hi, g_initW_hi); SYM(initW_lo, g_initW_lo);
  SYM(zW_hi, g_zW_hi); SYM(zW_lo, g_zW_lo);
  SYM(outW_hi, g_outW_hi); SYM(outW_lo, g_outW_lo);
  SYM(hn_hi, g_hn_hi); SYM(hn_lo, g_hn_lo);
  SYM(z_hi, g_z_hi); SYM(z_lo, g_z_lo);
  SYM(h0_hi, g_h0_hi); SYM(h0_lo, g_h0_lo);
  SYM(hs_hi, g_hs_hi); SYM(hs_lo, g_hs_lo);
  SYM(ce, g_ce); SYM(zml, g_zml); SYM(initb, g_init); SYM(zp, g_zp); SYM(cd, g_cd);
  SYM(db, g_db); SYM(eb, g_eb); SYM(dWih2, g_dWih2); SYM(eWih2, g_eWih2);
#undef SYM

  cvt_all<<<(unsigned)((L9 + 255) / 256), 256>>>(
      dec_Whh, enc_Whh_f, enc_Whh_b, enc_out_W, init_W, dec_Wih, out_W,
      dec_b, enc_b_f, enc_b_b);
  cvt_encwih<<<16, 256>>>(enc_Wih_f, enc_Wih_b);

  // ---- bidirectional encoder, fused GEMM+LSTM, 128 steps ----
  for (int t = 0; t < NT; t++) {
    int p = t & 1, q = 1 - p;
    GArg f, bw;
    f.Ahi = hn_hi + (size_t)p * HNBUF;        f.Alo = hn_lo + (size_t)p * HNBUF;
    f.Whi = eWf_hi; f.Wlo = eWf_lo;
    f.bias = eb;                               // permuted enc_b_f
    f.wih2 = eWih2; f.data = data; f.lengths = lengths;
    f.cstate = ce; f.cstride = NHE;
    f.ohi = hn_hi + (size_t)q * HNBUF;         f.olo = hn_lo + (size_t)q * HNBUF;
    f.ostride = 2 * NHE; f.mode = 1; f.t = t; f.dir = 0;
    bw = f;
    bw.Ahi = f.Ahi + NHE; bw.Alo = f.Alo + NHE;
    bw.Whi = eWb_hi; bw.Wlo = eWb_lo;
    bw.bias = eb + NGE;
    bw.wih2 = eWih2 + NGE;
    bw.cstate = ce + (size_t)NB * NHE;
    bw.ohi = f.ohi + NHE; bw.olo = f.olo + NHE;
    bw.dir = 1;
    run_gemm(f, bw, 2 * NHE, NGE, NGE, NHE, NB, 2);
  }

  // ---- latent ----
  {
    GArg a;
    a.Ahi = hn_hi; a.Alo = hn_lo;              // final buffer = buf 0
    a.Whi = eOut_hi; a.Wlo = eOut_lo;
    a.bias = enc_out_b; a.C = zml; a.mode = 0;
    run_gemm(a, a, 2 * NHE, 2 * NZ, 2 * NZ, 2 * NHE, NB, 1);
  }
  latent_kernel<<<256, 256>>>(eps, zm_out, zl_out);
  {
    GArg a;
    a.Ahi = z_hi; a.Alo = z_lo;
    a.Whi = initW_hi; a.Wlo = initW_lo;
    a.bias = init_b; a.C = initb; a.mode = 0;
    run_gemm(a, a, NZ, 2 * NHD, 2 * NHD, NZ, NB, 1);
  }
  initsplit_kernel<<<4096, 256>>>();
  {
    GArg a;
    a.Ahi = z_hi; a.Alo = z_lo;
    a.Whi = zW_hi; a.Wlo = zW_lo;
    a.bias = db;                               // permuted dec_b
    a.C = zp; a.mode = 0;
    run_gemm(a, a, NZ, NGD, NGD, NZ, NB, 1);
  }

  // ---- decoder, fused GEMM+LSTM, 128 steps ----
  for (int t = 0; t < NT; t++) {
    GArg a;
    a.Ahi = t ? (hs_hi + (size_t)(t - 1) * NHD) : h0_hi;
    a.Alo = t ? (hs_lo + (size_t)(t - 1) * NHD) : h0_lo;
    a.Whi = dWhh_hi; a.Wlo = dWhh_lo;
    a.Cadd = zp;                               // permuted zp (+dec_b)
    a.wih2 = dWih2; a.data = data;
    a.cstate = cd; a.cstride = NHD;
    a.ohi = hs_hi + (size_t)t * NHD; a.olo = hs_lo + (size_t)t * NHD;
    a.ostride = (long)NT * NHD;
    a.mode = 2; a.t = t;
    size_t lda = t ? (size_t)NT * NHD : (size_t)NHD;
    run_gemm(a, a, lda, NGD, NGD, NHD, NB, 1);
  }

  // ---- output projection ----
  {
    GArg a;
    a.Ahi = hs_hi; a.Alo = hs_lo;
    a.Whi = outW_hi; a.Wlo = outW_lo;
    a.bias = out_b; a.C = params; a.mode = 0;
    run_gemm(a, a, NHD, NOUTD, NOUTD, NHD, NB * NT, 1);
  }
}

// round 7
// speedup vs baseline: 1.3518x; 1.3518x over previous
#include <cuda_runtime.h>
#include <cuda_bf16.h>
#include <math.h>
#include <stdint.h>

#define NB 512
#define NT 128
#define NHE 512
#define NGE 2048
#define NZ 128
#define NHD 2048
#define NGD 8192
#define NOUTD 123
#define DATALD 129
#define DLD 133

#if !defined(__CUDA_ARCH__)
#define USE_TC 1
#elif defined(__CUDA_ARCH_FEAT_SM103_ALL) || defined(__CUDA_ARCH_FEAT_SM100_ALL)
#define USE_TC 1
#else
#define USE_TC 0
#endif

// ---------------- device scratch ----------------
__device__ __nv_bfloat16 g_dWhh_hi[NGD * NHD];
__device__ __nv_bfloat16 g_dWhh_lo[NGD * NHD];
__device__ __nv_bfloat16 g_eWf_hi[NGE * NHE];
__device__ __nv_bfloat16 g_eWf_lo[NGE * NHE];
__device__ __nv_bfloat16 g_eWb_hi[NGE * NHE];
__device__ __nv_bfloat16 g_eWb_lo[NGE * NHE];
__device__ __nv_bfloat16 g_eOut_hi[2 * NZ * 2 * NHE];
__device__ __nv_bfloat16 g_eOut_lo[2 * NZ * 2 * NHE];
__device__ __nv_bfloat16 g_initW_hi[2 * NHD * NZ];
__device__ __nv_bfloat16 g_initW_lo[2 * NHD * NZ];
__device__ __nv_bfloat16 g_zW_hi[NGD * NZ];
__device__ __nv_bfloat16 g_zW_lo[NGD * NZ];
__device__ __nv_bfloat16 g_outW_hi[NOUTD * NHD];
__device__ __nv_bfloat16 g_outW_lo[NOUTD * NHD];
__device__ float2 g_dWih2[NGD];

__device__ __nv_bfloat16 g_hn_hi[NB * 2 * NHE];
__device__ __nv_bfloat16 g_hn_lo[NB * 2 * NHE];
__device__ float g_ce[2 * NB * NHE];
__device__ float g_Ge[2 * NB * NGE];
__device__ float g_zml[NB * 2 * NZ];
__device__ __nv_bfloat16 g_z_hi[NB * NZ];
__device__ __nv_bfloat16 g_z_lo[NB * NZ];
__device__ float g_init[NB * 2 * NHD];
__device__ __nv_bfloat16 g_h0_hi[NB * NHD];
__device__ __nv_bfloat16 g_h0_lo[NB * NHD];
__device__ float g_cd[NB * NHD];
__device__ float g_zp[NB * NGD];
__device__ float g_G[NB * NGD];
__device__ __nv_bfloat16 g_hs_hi[(size_t)NB * NT * NHD];
__device__ __nv_bfloat16 g_hs_lo[(size_t)NB * NT * NHD];

// ---------------- helpers ----------------
__device__ __forceinline__ uint32_t smem_u32(const void* p) {
  uint32_t a;
  asm("{ .reg .u64 t; cvta.to.shared.u64 t, %1; cvt.u32.u64 %0, t; }" : "=r"(a) : "l"(p));
  return a;
}
__device__ __forceinline__ void cp16(uint32_t dst, const void* src, bool ok) {
  int sz = ok ? 16 : 0;
  asm volatile("cp.async.cg.shared.global [%0], [%1], 16, %2;\n"
               :: "r"(dst), "l"(src), "r"(sz) : "memory");
}
__device__ __forceinline__ void cp_commit() { asm volatile("cp.async.commit_group;" ::: "memory"); }
template <int N>
__device__ __forceinline__ void cp_wait() { asm volatile("cp.async.wait_group %0;" :: "n"(N) : "memory"); }
__device__ __forceinline__ float sigf(float x) { return 1.0f / (1.0f + expf(-x)); }
__device__ __forceinline__ void split_bf16(float x, __nv_bfloat16* hi, __nv_bfloat16* lo) {
  __nv_bfloat16 h = __float2bfloat16(x);
  *hi = h;
  *lo = __float2bfloat16(x - __bfloat162float(h));
}

struct GArg {
  const __nv_bfloat16 *Ahi, *Alo;  // [M][K] stride lda
  const __nv_bfloat16 *Whi, *Wlo;  // [N][K] packed
  const float *bias;
  const float *Cadd;
  float *C;
};

#define GS 197632u   // 1024 + 3*65536

#if USE_TC
// =====================================================================
// tcgen05 path (sm_103a cubin — the one that actually executes)
// =====================================================================
__device__ __forceinline__ uint32_t elect_one_pred() {
  uint32_t pred;
  asm volatile(
      "{\n\t.reg .pred p;\n\telect.sync _|p, 0xFFFFFFFF;\n\tselp.b32 %0, 1, 0, p;\n\t}"
      : "=r"(pred));
  return pred;
}
__device__ __forceinline__ uint32_t ctarank() {
  uint32_t r; asm("mov.u32 %0, %%cluster_ctarank;" : "=r"(r)); return r;
}
#define MBARRIER_INIT(addr, cnt) \
  asm volatile("mbarrier.init.shared.b64 [%0], %1;" :: "r"((uint32_t)(addr)), "r"((uint32_t)(cnt)) : "memory")
#define MBARRIER_WAIT_PARITY(addr, par) do {                                        \
  uint32_t _m = (uint32_t)(addr); uint32_t _p = (uint32_t)(par);                    \
  asm volatile("{\n\t.reg .pred P1;\n\t"                                            \
    "WL_%=:\n\t"                                                                    \
    "mbarrier.try_wait.parity.acquire.cta.shared::cta.b64 P1, [%0], %1, 0x989680;\n\t" \
    "@P1 bra.uni WD_%=;\n\t"                                                        \
    "bra.uni WL_%=;\n\t"                                                            \
    "WD_%=:\n\t}" :: "r"(_m), "r"(_p) : "memory");                                  \
} while (0)
#define MBARRIER_WAIT_PARITY_CLU(addr, par) do {                                    \
  uint32_t _m = (uint32_t)(addr); uint32_t _p = (uint32_t)(par);                    \
  asm volatile("{\n\t.reg .pred P1;\n\t"                                            \
    "WLc_%=:\n\t"                                                                   \
    "mbarrier.try_wait.parity.acquire.cluster.shared::cta.b64 P1, [%0], %1, 0x989680;\n\t" \
    "@P1 bra.uni WDc_%=;\n\t"                                                       \
    "bra.uni WLc_%=;\n\t"                                                           \
    "WDc_%=:\n\t}" :: "r"(_m), "r"(_p) : "memory");                                 \
} while (0)
#define MBARRIER_ARRIVE_CLUSTER(localaddr, rank) \
  asm volatile("{\n\t.reg .b32 ra;\n\t" \
               "mapa.shared::cluster.u32 ra, %0, %1;\n\t" \
               "mbarrier.arrive.release.cluster.shared::cluster.b64 _, [ra];\n\t}" \
               :: "r"((uint32_t)(localaddr)), "r"((uint32_t)(rank)) : "memory")
#define CLUSTER_SYNC() do { \
  asm volatile("barrier.cluster.arrive.aligned;" ::: "memory"); \
  asm volatile("barrier.cluster.wait.aligned;" ::: "memory"); \
} while (0)

#define TCGEN05_ALLOC(sm, n) \
  asm volatile("tcgen05.alloc.cta_group::1.sync.aligned.shared::cta.b32 [%0], %1;" \
               :: "r"((uint32_t)(sm)), "r"((uint32_t)(n)) : "memory")
#define TCGEN05_DEALLOC(t, n) \
  asm volatile("tcgen05.dealloc.cta_group::1.sync.aligned.b32 %0, %1;" :: "r"(t), "r"((uint32_t)(n)))
#define TCGEN05_RELINQ() \
  asm volatile("tcgen05.relinquish_alloc_permit.cta_group::1.sync.aligned;")
#define TCGEN05_ALLOC_CG2(sm, n) \
  asm volatile("tcgen05.alloc.cta_group::2.sync.aligned.shared::cta.b32 [%0], %1;" \
               :: "r"((uint32_t)(sm)), "r"((uint32_t)(n)) : "memory")
#define TCGEN05_DEALLOC_CG2(t, n) \
  asm volatile("tcgen05.dealloc.cta_group::2.sync.aligned.b32 %0, %1;" :: "r"(t), "r"((uint32_t)(n)))
#define TCGEN05_RELINQ_CG2() \
  asm volatile("tcgen05.relinquish_alloc_permit.cta_group::2.sync.aligned;")
#define TCGEN05_COMMIT(mb) \
  asm volatile("tcgen05.commit.cta_group::1.mbarrier::arrive::one.shared::cluster.b64 [%0];" \
               :: "r"((uint32_t)(mb)) : "memory")
#define TCGEN05_COMMIT_MC_CG2(mb, mask) \
  asm volatile("tcgen05.commit.cta_group::2.mbarrier::arrive::one.shared::cluster.multicast::cluster.b64 [%0], %1;" \
               :: "r"((uint32_t)(mb)), "h"((uint16_t)(mask)) : "memory")
#define TCGEN05_FENCE_AFTER()  asm volatile("tcgen05.fence::after_thread_sync;" ::: "memory")
#define TCGEN05_FENCE_BEFORE() asm volatile("tcgen05.fence::before_thread_sync;" ::: "memory")
#define TCGEN05_WAIT_LD()      asm volatile("tcgen05.wait::ld.sync.aligned;" ::: "memory")
#define TCGEN05_LD_32X32B_X32(r, addr)                                            \
  asm volatile(                                                                   \
      "tcgen05.ld.sync.aligned.32x32b.x32.b32 "                                   \
      "{%0, %1, %2, %3, %4, %5, %6, %7, %8, %9, %10, %11, %12, %13, %14, %15, "   \
      " %16, %17, %18, %19, %20, %21, %22, %23, %24, %25, %26, %27, %28, %29, %30, %31}, [%32];" \
      : "=r"((r)[0]), "=r"((r)[1]), "=r"((r)[2]), "=r"((r)[3]),                   \
        "=r"((r)[4]), "=r"((r)[5]), "=r"((r)[6]), "=r"((r)[7]),                   \
        "=r"((r)[8]), "=r"((r)[9]), "=r"((r)[10]), "=r"((r)[11]),                 \
        "=r"((r)[12]), "=r"((r)[13]), "=r"((r)[14]), "=r"((r)[15]),               \
        "=r"((r)[16]), "=r"((r)[17]), "=r"((r)[18]), "=r"((r)[19]),               \
        "=r"((r)[20]), "=r"((r)[21]), "=r"((r)[22]), "=r"((r)[23]),               \
        "=r"((r)[24]), "=r"((r)[25]), "=r"((r)[26]), "=r"((r)[27]),               \
        "=r"((r)[28]), "=r"((r)[29]), "=r"((r)[30]), "=r"((r)[31])                \
      : "r"(addr))

static constexpr unsigned long long SMEM_DESC_BASE_SW128 =
    (2ull << 61) | (1ull << 46) | (64ull << 32) | (1ull << 16);
#define MAKE_SMEM_DESC(a) (SMEM_DESC_BASE_SW128 | ((unsigned long long)((a) >> 4) & 0x3FFF))

template <int TN>
__device__ __forceinline__ void mma_cg1(uint32_t d, unsigned long long a,
                                        unsigned long long b, uint32_t en) {
  constexpr uint32_t idesc =
      (1u << 4) | (1u << 7) | (1u << 10) | ((TN / 8u) << 17) | (8u << 24);
  asm volatile(
      "{\n\t.reg .pred p;\n\tsetp.ne.u32 p, %4, 0;\n\t"
      "tcgen05.mma.cta_group::1.kind::f16 [%0], %1, %2, %3, {%5, %5, %5, %5}, p;\n\t}"
      :: "r"(d), "l"(a), "l"(b), "r"(idesc), "r"(en), "r"(0u) : "memory");
}
__device__ __forceinline__ void mma_cg2(uint32_t d, unsigned long long a,
                                        unsigned long long b, uint32_t en) {
  constexpr uint32_t idesc =
      (1u << 4) | (1u << 7) | (1u << 10) | ((256u / 8u) << 17) | (16u << 24);
  asm volatile(
      "{\n\t.reg .pred p;\n\tsetp.ne.u32 p, %4, 0;\n\t"
      "tcgen05.mma.cta_group::2.kind::f16 [%0], %1, %2, %3, "
      "{%5, %5, %5, %5, %5, %5, %5, %5}, p;\n\t}"
      :: "r"(d), "l"(a), "l"(b), "r"(idesc), "r"(en), "r"(0u) : "memory");
}

// stage layout: Ahi@0(16K), Alo@16K, Bhi@32K(BROWS*128), Blo after
template <int BROWS>
__device__ __forceinline__ void load_stage(
    uint32_t sbase, uint32_t stb, int stage, int ci,
    const __nv_bfloat16* Ahi, const __nv_bfloat16* Alo,
    const __nv_bfloat16* Whi, const __nv_bfloat16* Wlo,
    size_t lda, int m0, int n0, int N, int K, int tid)
{
  const uint32_t base = sbase + (uint32_t)stage * stb;
  const int k0 = ci << 6;
#pragma unroll
  for (int it = 0; it < 4; ++it) {
    int idx = tid + (it << 8);
    int row = idx >> 3, c = idx & 7;
    uint32_t off = (uint32_t)((row << 7) + (c << 4));
    off ^= ((off >> 3) & 0x70);
    size_t so = (size_t)(m0 + row) * lda + (size_t)k0 + (c << 3);
    cp16(base + off, Ahi + so, true);
    cp16(base + 16384u + off, Alo + so, true);
  }
#pragma unroll
  for (int it = 0; it < BROWS / 32; ++it) {
    int idx = tid + (it << 8);
    int row = idx >> 3, c = idx & 7;
    int n = n0 + row;
    bool ok = (n < N);
    size_t so = (size_t)(ok ? n : 0) * (size_t)K + (size_t)k0 + (c << 3);
    uint32_t off = (uint32_t)((row << 7) + (c << 4));
    off ^= ((off >> 3) & 0x70);
    cp16(base + 32768u + off, Whi + so, ok);
    cp16(base + 32768u + (uint32_t)BROWS * 128u + off, Wlo + so, ok);
  }
  cp_commit();
}

template <int TN, int BROWS, bool CG2>
__device__ __forceinline__ void mma_chunk(uint32_t sbase, uint32_t stb,
                                          int stage, uint32_t tmem, bool first) {
  uint32_t base = sbase + (uint32_t)stage * stb;
  unsigned long long dAh = MAKE_SMEM_DESC(base);
  unsigned long long dAl = MAKE_SMEM_DESC(base + 16384u);
  unsigned long long dBh = MAKE_SMEM_DESC(base + 32768u);
  unsigned long long dBl = MAKE_SMEM_DESC(base + 32768u + (uint32_t)BROWS * 128u);
#pragma unroll
  for (int ks = 0; ks < 4; ++ks) {
    unsigned long long o = (unsigned long long)(2 * ks);
    if (CG2) {
      mma_cg2(tmem, dAh + o, dBh + o, (first && ks == 0) ? 0u : 1u);
      mma_cg2(tmem, dAh + o, dBl + o, 1u);
      mma_cg2(tmem, dAl + o, dBh + o, 1u);
    } else {
      mma_cg1<TN>(tmem, dAh + o, dBh + o, (first && ks == 0) ? 0u : 1u);
      mma_cg1<TN>(tmem, dAh + o, dBl + o, 1u);
      mma_cg1<TN>(tmem, dAl + o, dBh + o, 1u);
    }
  }
}

// ---------------- cg1 GEMM: 128 x TN tiles, S-stage pipeline ----------------
template <int TN, int S>
__global__ void __launch_bounds__(256, 1) gemm3(GArg a0, GArg a1, size_t lda,
                                                size_t ldc, int N, int K) {
  extern __shared__ __align__(1024) char smem[];
  const int tid = threadIdx.x;
  const uint32_t sb = smem_u32(smem);
  const GArg g = blockIdx.z ? a1 : a0;
  const int m0 = blockIdx.y * 128;
  const int n0 = blockIdx.x * TN;
  const uint32_t stb = 32768u + (uint32_t)TN * 256u;

  if (tid == 0)
    for (int s = 0; s < S; ++s) MBARRIER_INIT(sb + 16 + 8 * s, 1);
  if (tid < 32) TCGEN05_ALLOC(sb, TN);
  __syncthreads();
  uint32_t tmem;
  asm volatile("ld.shared.b32 %0, [%1];" : "=r"(tmem) : "r"(sb));

  const int nch = K >> 6;
  for (int j = 0; j < S; ++j) {
    if (j < nch) load_stage<TN>(sb + 1024u, stb, j, j, g.Ahi, g.Alo, g.Whi, g.Wlo,
                                lda, m0, n0, N, K, tid);
    else cp_commit();
  }
  for (int i = 0; i < nch; ++i) {
    const int s = i % S;
    if (i >= 1) {
      int pc = i - 1, nc = pc + S;
      if (nc < nch) {
        MBARRIER_WAIT_PARITY(sb + 16 + 8 * (pc % S), (pc / S) & 1);
        load_stage<TN>(sb + 1024u, stb, pc % S, nc, g.Ahi, g.Alo, g.Whi, g.Wlo,
                       lda, m0, n0, N, K, tid);
      } else cp_commit();
    }
    cp_wait<S - 1>();
    asm volatile("fence.proxy.async.shared::cta;" ::: "memory");
    __syncthreads();
    if (tid < 32 && elect_one_pred()) {
      mma_chunk<TN, TN, false>(sb + 1024u, stb, s, tmem, i == 0);
      TCGEN05_COMMIT(sb + 16 + 8 * s);
    }
  }
  MBARRIER_WAIT_PARITY(sb + 16 + 8 * ((nch - 1) % S), ((nch - 1) / S) & 1);
  TCGEN05_FENCE_AFTER();

  {
    const int wq = (tid >> 5) & 3, wg = tid >> 7, lane = tid & 31;
    const size_t m = (size_t)m0 + (size_t)(wq * 32 + lane);
    float* crow = g.C + m * ldc;
    const float* arow = g.Cadd ? (g.Cadd + m * ldc) : (const float*)0;
    for (int c0 = wg * (TN / 2); c0 < (wg + 1) * (TN / 2); c0 += 32) {
      int n = n0 + c0;
      if (n >= N) break;
      uint32_t r[32];
      TCGEN05_LD_32X32B_X32(r, tmem + c0);
      TCGEN05_WAIT_LD();
      if (((ldc & 3) == 0) && (n + 32 <= N)) {
#pragma unroll
        for (int q = 0; q < 8; ++q) {
          float4 v;
          v.x = __uint_as_float(r[4 * q + 0]);
          v.y = __uint_as_float(r[4 * q + 1]);
          v.z = __uint_as_float(r[4 * q + 2]);
          v.w = __uint_as_float(r[4 * q + 3]);
          if (g.bias) {
            float4 bv = *(const float4*)(g.bias + n + 4 * q);
            v.x += bv.x; v.y += bv.y; v.z += bv.z; v.w += bv.w;
          }
          if (arow) {
            float4 av = *(const float4*)(arow + n + 4 * q);
            v.x += av.x; v.y += av.y; v.z += av.z; v.w += av.w;
          }
          *(float4*)(crow + n + 4 * q) = v;
        }
      } else {
        for (int j = 0; j < 32 && n + j < N; ++j) {
          float v = __uint_as_float(r[j]);
          if (g.bias) v += g.bias[n + j];
          if (arow) v += arow[n + j];
          crow[n + j] = v;
        }
      }
    }
    TCGEN05_FENCE_BEFORE();
  }
  __syncthreads();
  if (tid < 32) { TCGEN05_RELINQ(); TCGEN05_DEALLOC(tmem, TN); }
}

// ---------------- cg2 decoder GEMM: cluster pair computes 256x256 ----------
__global__ void __launch_bounds__(256, 1) __cluster_dims__(2, 1, 1)
gemm_dec(const __nv_bfloat16* Ahi, const __nv_bfloat16* Alo, size_t lda,
         const __nv_bfloat16* Whi, const __nv_bfloat16* Wlo,
         const float* zp, float* G) {
  extern __shared__ __align__(1024) char smem[];
  const int tid = threadIdx.x;
  const uint32_t sb = smem_u32(smem);
  const uint32_t rank = ctarank();
  const int n0 = (int)(blockIdx.x >> 1) * 256;
  const int mA = (int)blockIdx.y * 256 + (int)rank * 128;
  const int nB = n0 + (int)rank * 128;
  const uint32_t stb = 65536u;
  const int nch = NHD >> 6;  // 32

  if (tid == 0)
    for (int s = 0; s < 3; ++s) {
      MBARRIER_INIT(sb + 16 + 8 * s, 2);   // full (2 arrivals, lives on rank0)
      MBARRIER_INIT(sb + 48 + 8 * s, 1);   // done (multicast commit)
    }
  if (tid < 32) TCGEN05_ALLOC_CG2(sb + 8, 256);
  __syncthreads();
  uint32_t tmem;
  asm volatile("ld.shared.b32 %0, [%1];" : "=r"(tmem) : "r"(sb + 8));
  CLUSTER_SYNC();

  for (int j = 0; j < 3; ++j)
    load_stage<128>(sb + 1024u, stb, j, j, Ahi, Alo, Whi, Wlo, lda, mA, nB,
                    NGD, NHD, tid);

  for (int i = 0; i < nch; ++i) {
    const int s = i % 3;
    if (i >= 1) {
      int pc = i - 1, nc = pc + 3;
      if (nc < nch) {
        MBARRIER_WAIT_PARITY(sb + 48 + 8 * (pc % 3), (pc / 3) & 1);
        load_stage<128>(sb + 1024u, stb, pc % 3, nc, Ahi, Alo, Whi, Wlo, lda,
                        mA, nB, NGD, NHD, tid);
      } else cp_commit();
    }
    cp_wait<2>();
    asm volatile("fence.proxy.async.shared::cta;" ::: "memory");
    __syncthreads();
    if (tid == 0) MBARRIER_ARRIVE_CLUSTER(sb + 16 + 8 * s, 0);
    if (rank == 0 && tid < 32 && elect_one_pred()) {
      MBARRIER_WAIT_PARITY_CLU(sb + 16 + 8 * s, (i / 3) & 1);
      mma_chunk<256, 128, true>(sb + 1024u, stb, s, tmem, i == 0);
      TCGEN05_COMMIT_MC_CG2(sb + 48 + 8 * s, 0x3);
    }
  }
  MBARRIER_WAIT_PARITY(sb + 48 + 8 * ((nch - 1) % 3), ((nch - 1) / 3) & 1);
  TCGEN05_FENCE_AFTER();

  {
    const int wq = (tid >> 5) & 3, wg = tid >> 7, lane = tid & 31;
    const size_t m = (size_t)mA + (size_t)(wq * 32 + lane);
    float* crow = G + m * NGD;
    const float* arow = zp + m * NGD;
    for (int c0 = wg * 128; c0 < wg * 128 + 128; c0 += 32) {
      int n = n0 + c0;
      uint32_t r[32];
      TCGEN05_LD_32X32B_X32(r, tmem + c0);
      TCGEN05_WAIT_LD();
#pragma unroll
      for (int q = 0; q < 8; ++q) {
        float4 v;
        v.x = __uint_as_float(r[4 * q + 0]);
        v.y = __uint_as_float(r[4 * q + 1]);
        v.z = __uint_as_float(r[4 * q + 2]);
        v.w = __uint_as_float(r[4 * q + 3]);
        float4 av = *(const float4*)(arow + n + 4 * q);
        v.x += av.x; v.y += av.y; v.z += av.z; v.w += av.w;
        *(float4*)(crow + n + 4 * q) = v;
      }
    }
    TCGEN05_FENCE_BEFORE();
  }
  __syncthreads();
  CLUSTER_SYNC();
  if (tid < 32) { TCGEN05_RELINQ_CG2(); TCGEN05_DEALLOC_CG2(tmem, 256); }
  CLUSTER_SYNC();
}

#else
// =====================================================================
// Naive fallback (sm_103 non-a pass; never selected at runtime)
// =====================================================================
template <int TN, int S>
__global__ void __launch_bounds__(256, 1) gemm3(GArg a0, GArg a1, size_t lda,
                                                size_t ldc, int N, int K) {
  const GArg g = blockIdx.z ? a1 : a0;
  int m0 = blockIdx.y * 128, n0 = blockIdx.x * TN;
  for (int e = threadIdx.x; e < 128 * TN; e += 256) {
    int m = m0 + e / TN, n = n0 + e % TN;
    if (n >= N) continue;
    float s = 0.f;
    const __nv_bfloat16 *ah = g.Ahi + (size_t)m * lda, *al = g.Alo + (size_t)m * lda;
    const __nv_bfloat16 *wh = g.Whi + (size_t)n * K, *wl = g.Wlo + (size_t)n * K;
    for (int k = 0; k < K; ++k)
      s += (__bfloat162float(ah[k]) + __bfloat162float(al[k])) *
           (__bfloat162float(wh[k]) + __bfloat162float(wl[k]));
    if (g.bias) s += g.bias[n];
    if (g.Cadd) s += g.Cadd[(size_t)m * ldc + n];
    g.C[(size_t)m * ldc + n] = s;
  }
}
__global__ void __launch_bounds__(256, 1) gemm_dec(
    const __nv_bfloat16* Ahi, const __nv_bfloat16* Alo, size_t lda,
    const __nv_bfloat16* Whi, const __nv_bfloat16* Wlo,
    const float* zp, float* G) {
  int m0 = blockIdx.y * 256 + (blockIdx.x & 1) * 128;
  int n0 = (blockIdx.x >> 1) * 256;
  for (int e = threadIdx.x; e < 128 * 256; e += 256) {
    int m = m0 + e / 256, n = n0 + e % 256;
    float s = 0.f;
    const __nv_bfloat16 *ah = Ahi + (size_t)m * lda, *al = Alo + (size_t)m * lda;
    const __nv_bfloat16 *wh = Whi + (size_t)n * NHD, *wl = Wlo + (size_t)n * NHD;
    for (int k = 0; k < NHD; ++k)
      s += (__bfloat162float(ah[k]) + __bfloat162float(al[k])) *
           (__bfloat162float(wh[k]) + __bfloat162float(wl[k]));
    G[(size_t)m * NGD + n] = s + zp[(size_t)m * NGD + n];
  }
}
#endif  // USE_TC

// ---------------- cvt_all ----------------
#define SEG0 16777216L
#define SEG1 (SEG0 + 1048576L)
#define SEG2 (SEG1 + 1048576L)
#define SEG3 (SEG2 + 262144L)
#define SEG4 (SEG3 + 524288L)
#define SEG5 (SEG4 + 1048576L)
#define SEG6 (SEG5 + 251904L)
#define SEG7 (SEG6 + 524288L)
#define SEG8 (SEG7 + 8192L)
__global__ void cvt_all(const float* __restrict__ dWhh, const float* __restrict__ eWf,
                        const float* __restrict__ eWb, const float* __restrict__ eOut,
                        const float* __restrict__ initW, const float* __restrict__ decWih,
                        const float* __restrict__ outW) {
  long idx = blockIdx.x * 256L + threadIdx.x;
  if (idx >= SEG8) return;
  if (idx < SEG0) {
    split_bf16(dWhh[idx], &g_dWhh_hi[idx], &g_dWhh_lo[idx]);
  } else if (idx < SEG1) {
    long i = idx - SEG0; split_bf16(eWf[i], &g_eWf_hi[i], &g_eWf_lo[i]);
  } else if (idx < SEG2) {
    long i = idx - SEG1; split_bf16(eWb[i], &g_eWb_hi[i], &g_eWb_lo[i]);
  } else if (idx < SEG3) {
    long i = idx - SEG2; split_bf16(eOut[i], &g_eOut_hi[i], &g_eOut_lo[i]);
  } else if (idx < SEG4) {
    long i = idx - SEG3; split_bf16(initW[i], &g_initW_hi[i], &g_initW_lo[i]);
  } else if (idx < SEG5) {
    long i = idx - SEG4;
    long n = i >> 7, k = i & 127;
    split_bf16(decWih[n * DLD + 5 + k], &g_zW_hi[i], &g_zW_lo[i]);
  } else if (idx < SEG6) {
    long i = idx - SEG5; split_bf16(outW[i], &g_outW_hi[i], &g_outW_lo[i]);
  } else if (idx < SEG7) {
    long i = idx - SEG6;
    g_hn_hi[i] = __float2bfloat16(0.0f);
    g_hn_lo[i] = __float2bfloat16(0.0f);
    g_ce[i] = 0.0f;
  } else {
    int r = (int)(idx - SEG7);
    g_dWih2[r] = make_float2(decWih[(long)r * DLD], decWih[(long)r * DLD + 1]);
  }
}

// ---------------- gate / small kernels ----------------
__global__ void enc_gate_kernel(const float* __restrict__ data,
                                const int* __restrict__ lengths,
                                const float* __restrict__ Wih_f,
                                const float* __restrict__ Wih_b, int t) {
  int idx = blockIdx.x * blockDim.x + threadIdx.x;
  int dir = idx >> 18;
  int rr = idx & ((1 << 18) - 1);
  int b = rr >> 9;
  int j = rr & 511;
  int L = lengths[b];
  L = L < 1 ? 1 : (L > NT ? NT : L);
  if (t >= L) return;
  int ti = dir ? (L - 1 - t) : t;
  float x0 = data[((size_t)b * DATALD + ti + 1) * 2 + 0];
  float x1 = data[((size_t)b * DATALD + ti + 1) * 2 + 1];
  const float* Wih = dir ? Wih_b : Wih_f;
  const float* G = g_Ge + (size_t)(dir * NB + b) * NGE;
  float pi = G[j]           + x0 * Wih[2 * j]               + x1 * Wih[2 * j + 1];
  float pf = G[NHE + j]     + x0 * Wih[2 * (NHE + j)]       + x1 * Wih[2 * (NHE + j) + 1];
  float pg = G[2 * NHE + j] + x0 * Wih[2 * (2 * NHE + j)]   + x1 * Wih[2 * (2 * NHE + j) + 1];
  float po = G[3 * NHE + j] + x0 * Wih[2 * (3 * NHE + j)]   + x1 * Wih[2 * (3 * NHE + j) + 1];
  int ci = (dir * NB + b) * NHE + j;
  float c = g_ce[ci];
  float c2 = sigf(pf) * c + sigf(pi) * tanhf(pg);
  float h2 = sigf(po) * tanhf(c2);
  g_ce[ci] = c2;
  int hidx = b * (2 * NHE) + dir * NHE + j;
  split_bf16(h2, &g_hn_hi[hidx], &g_hn_lo[hidx]);
}

__global__ void latent_kernel(const float* __restrict__ eps,
                              float* __restrict__ zm_out,
                              float* __restrict__ zl_out) {
  int idx = blockIdx.x * blockDim.x + threadIdx.x;
  int b = idx >> 7, k = idx & 127;
  float zm = g_zml[b * 256 + k];
  float zl = g_zml[b * 256 + 128 + k];
  zm_out[idx] = zm;
  zl_out[idx] = zl;
  float z = zm + expf(0.5f * zl) * eps[idx];
  split_bf16(z, &g_z_hi[idx], &g_z_lo[idx]);
}

__global__ void initsplit_kernel() {
  int idx = blockIdx.x * blockDim.x + threadIdx.x;
  int b = idx >> 11, j = idx & 2047;
  float h0 = tanhf(g_init[b * (2 * NHD) + j]);
  float c0 = tanhf(g_init[b * (2 * NHD) + NHD + j]);
  g_cd[idx] = c0;
  split_bf16(h0, &g_h0_hi[idx], &g_h0_lo[idx]);
}

__global__ void dec_gate_kernel(const float* __restrict__ data, int t) {
  int idx = blockIdx.x * blockDim.x + threadIdx.x;
  int b = idx >> 11, j = idx & 2047;
  float x0 = data[((size_t)b * DATALD + t) * 2 + 0];
  float x1 = data[((size_t)b * DATALD + t) * 2 + 1];
  const float* G = g_G + (size_t)b * NGD;
  int r0 = j, r1 = j + NHD, r2 = j + 2 * NHD, r3 = j + 3 * NHD;
  float2 w0 = g_dWih2[r0], w1 = g_dWih2[r1], w2 = g_dWih2[r2], w3 = g_dWih2[r3];
  float pi = G[r0] + x0 * w0.x + x1 * w0.y;
  float pf = G[r1] + x0 * w1.x + x1 * w1.y;
  float pg = G[r2] + x0 * w2.x + x1 * w2.y;
  float po = G[r3] + x0 * w3.x + x1 * w3.y;
  float c = g_cd[idx];
  float c2 = sigf(pf) * c + sigf(pi) * tanhf(pg);
  float h2 = sigf(po) * tanhf(c2);
  g_cd[idx] = c2;
  size_t ho = ((size_t)b * NT + t) * NHD + j;
  split_bf16(h2, &g_hs_hi[ho], &g_hs_lo[ho]);
}

// ---------------- launch ----------------
static inline void run_gemm(const GArg& a0, const GArg& a1, size_t lda, size_t ldc,
                            int N, int K, int M, int nz) {
  dim3 grid((unsigned)((N + 127) / 128), (unsigned)(M / 128), (unsigned)nz);
  gemm3<128, 3><<<grid, 256, GS>>>(a0, a1, lda, ldc, N, K);
}

extern "C" void kernel_launch(void* const* d_in, const int* in_sizes, int n_in,
                              void* d_out, int out_size) {
  const float* data      = (const float*)d_in[0];
  const float* eps       = (const float*)d_in[1];
  const float* enc_Wih_f = (const float*)d_in[2];
  const float* enc_Whh_f = (const float*)d_in[3];
  const float* enc_b_f   = (const float*)d_in[4];
  const float* enc_Wih_b = (const float*)d_in[5];
  const float* enc_Whh_b = (const float*)d_in[6];
  const float* enc_b_b   = (const float*)d_in[7];
  const float* enc_out_W = (const float*)d_in[8];
  const float* enc_out_b = (const float*)d_in[9];
  const float* init_W    = (const float*)d_in[10];
  const float* init_b    = (const float*)d_in[11];
  const float* dec_Wih   = (const float*)d_in[12];
  const float* dec_Whh   = (const float*)d_in[13];
  const float* dec_b     = (const float*)d_in[14];
  const float* out_W     = (const float*)d_in[15];
  const float* out_b     = (const float*)d_in[16];
  const int*   lengths   = (const int*)d_in[17];

  float* out    = (float*)d_out;
  float* params = out;
  float* zm_out = out + (size_t)NB * NT * NOUTD;
  float* zl_out = zm_out + (size_t)NB * NT;

  cudaFuncSetAttribute(gemm3<128, 3>, cudaFuncAttributeMaxDynamicSharedMemorySize, GS);
  cudaFuncSetAttribute(gemm_dec, cudaFuncAttributeMaxDynamicSharedMemorySize, GS);

#define SYM(p, s) cudaGetSymbolAddress((void**)&p, s)
  __nv_bfloat16 *dWhh_hi, *dWhh_lo, *eWf_hi, *eWf_lo, *eWb_hi, *eWb_lo;
  __nv_bfloat16 *eOut_hi, *eOut_lo, *initW_hi, *initW_lo, *zW_hi, *zW_lo, *outW_hi, *outW_lo;
  __nv_bfloat16 *hn_hi, *hn_lo, *z_hi, *z_lo, *h0_hi, *h0_lo, *hs_hi, *hs_lo;
  float *Ge, *zml, *initb, *zp, *G;
  SYM(dWhh_hi, g_dWhh_hi); SYM(dWhh_lo, g_dWhh_lo);
  SYM(eWf_hi, g_eWf_hi); SYM(eWf_lo, g_eWf_lo);
  SYM(eWb_hi, g_eWb_hi); SYM(eWb_lo, g_eWb_lo);
  SYM(eOut_hi, g_eOut_hi); SYM(eOut_lo, g_eOut_lo);
  SYM(initW_hi, g_initW_hi); SYM(initW_lo, g_initW_lo);
  SYM(zW_hi, g_zW_hi); SYM(zW_lo, g_zW_lo);
  SYM(outW_hi, g_outW_hi); SYM(outW_lo, g_outW_lo);
  SYM(hn_hi, g_hn_hi); SYM(hn_lo, g_hn_lo);
  SYM(z_hi, g_z_hi); SYM(z_lo, g_z_lo);
  SYM(h0_hi, g_h0_hi); SYM(h0_lo, g_h0_lo);
  SYM(hs_hi, g_hs_hi); SYM(hs_lo, g_hs_lo);
  SYM(Ge, g_Ge); SYM(zml, g_zml); SYM(initb, g_init); SYM(zp, g_zp); SYM(G, g_G);
#undef SYM

  cvt_all<<<(unsigned)((SEG8 + 255) / 256), 256>>>(
      dec_Whh, enc_Whh_f, enc_Whh_b, enc_out_W, init_W, dec_Wih, out_W);

  // ---- bidirectional encoder, 128 steps ----
  for (int t = 0; t < NT; t++) {
    GArg f = {hn_hi, hn_lo, eWf_hi, eWf_lo, enc_b_f, nullptr, Ge};
    GArg bw = {hn_hi + NHE, hn_lo + NHE, eWb_hi, eWb_lo, enc_b_b, nullptr,
               Ge + (size_t)NB * NGE};
    run_gemm(f, bw, 2 * NHE, NGE, NGE, NHE, NB, 2);
    enc_gate_kernel<<<2048, 256>>>(data, lengths, enc_Wih_f, enc_Wih_b, t);
  }

  // ---- latent ----
  {
    GArg a = {hn_hi, hn_lo, eOut_hi, eOut_lo, enc_out_b, nullptr, zml};
    run_gemm(a, a, 2 * NHE, 2 * NZ, 2 * NZ, 2 * NHE, NB, 1);
  }
  latent_kernel<<<256, 256>>>(eps, zm_out, zl_out);
  {
    GArg a = {z_hi, z_lo, initW_hi, initW_lo, init_b, nullptr, initb};
    run_gemm(a, a, NZ, 2 * NHD, 2 * NHD, NZ, NB, 1);
  }
  initsplit_kernel<<<4096, 256>>>();
  {
    GArg a = {z_hi, z_lo, zW_hi, zW_lo, dec_b, nullptr, zp};
    run_gemm(a, a, NZ, NGD, NGD, NZ, NB, 1);
  }

  // ---- decoder, 128 steps (cg2 pair GEMM + gate) ----
  for (int t = 0; t < NT; t++) {
    const __nv_bfloat16* Ah = t ? (hs_hi + (size_t)(t - 1) * NHD) : h0_hi;
    const __nv_bfloat16* Al = t ? (hs_lo + (size_t)(t - 1) * NHD) : h0_lo;
    size_t lda = t ? (size_t)NT * NHD : (size_t)NHD;
    gemm_dec<<<dim3(64, 2), 256, GS>>>(Ah, Al, lda, dWhh_hi, dWhh_lo, zp, G);
    dec_gate_kernel<<<4096, 256>>>(data, t);
  }

  // ---- output projection ----
  {
    GArg a = {hs_hi, hs_lo, outW_hi, outW_lo, out_b, nullptr, params};
    run_gemm(a, a, NHD, NOUTD, NOUTD, NHD, NB * NT, 1);
  }
}

// round 9
// speedup vs baseline: 1.9691x; 1.4566x over previous
#include <cuda_runtime.h>
#include <cuda_bf16.h>
#include <math.h>
#include <stdint.h>

#define NB 512
#define NT 128
#define NHE 512
#define NGE 2048
#define NZ 128
#define NHD 2048
#define NGD 8192
#define NOUTD 123
#define DATALD 129
#define DLD 133

#if !defined(__CUDA_ARCH__)
#define USE_TC 1
#elif defined(__CUDA_ARCH_FEAT_SM103_ALL) || defined(__CUDA_ARCH_FEAT_SM100_ALL)
#define USE_TC 1
#else
#define USE_TC 0
#endif

// ---------------- device scratch ----------------
__device__ __nv_bfloat16 g_dWhh_hi[NGD * NHD];
__device__ __nv_bfloat16 g_dWhh_lo[NGD * NHD];
__device__ __nv_bfloat16 g_eWf_hi[NGE * NHE];
__device__ __nv_bfloat16 g_eWf_lo[NGE * NHE];
__device__ __nv_bfloat16 g_eWb_hi[NGE * NHE];
__device__ __nv_bfloat16 g_eWb_lo[NGE * NHE];
__device__ __nv_bfloat16 g_eOut_hi[2 * NZ * 2 * NHE];
__device__ __nv_bfloat16 g_eOut_lo[2 * NZ * 2 * NHE];
__device__ __nv_bfloat16 g_initW_hi[2 * NHD * NZ];
__device__ __nv_bfloat16 g_initW_lo[2 * NHD * NZ];
__device__ __nv_bfloat16 g_zW_hi[NGD * NZ];
__device__ __nv_bfloat16 g_zW_lo[NGD * NZ];
__device__ __nv_bfloat16 g_outW_hi[NOUTD * NHD];
__device__ __nv_bfloat16 g_outW_lo[NOUTD * NHD];
__device__ float2 g_dWih2[NGD];

__device__ __nv_bfloat16 g_hn_hi[NB * 2 * NHE];
__device__ __nv_bfloat16 g_hn_lo[NB * 2 * NHE];
__device__ float g_ce[2 * NB * NHE];
__device__ float g_Ge[2 * NB * NGE];
__device__ float g_zml[NB * 2 * NZ];
__device__ __nv_bfloat16 g_z_hi[NB * NZ];
__device__ __nv_bfloat16 g_z_lo[NB * NZ];
__device__ float g_init[NB * 2 * NHD];
__device__ __nv_bfloat16 g_h0_hi[NB * NHD];
__device__ __nv_bfloat16 g_h0_lo[NB * NHD];
__device__ float g_cd[NB * NHD];
__device__ float g_zp[NB * NGD];
__device__ float g_G[NB * NGD];
__device__ __nv_bfloat16 g_hs_hi[(size_t)NB * NT * NHD];
__device__ __nv_bfloat16 g_hs_lo[(size_t)NB * NT * NHD];

// ---------------- helpers ----------------
__device__ __forceinline__ uint32_t smem_u32(const void* p) {
  uint32_t a;
  asm("{ .reg .u64 t; cvta.to.shared.u64 t, %1; cvt.u32.u64 %0, t; }" : "=r"(a) : "l"(p));
  return a;
}
__device__ __forceinline__ void cp16(uint32_t dst, const void* src, bool ok) {
  int sz = ok ? 16 : 0;
  asm volatile("cp.async.cg.shared.global [%0], [%1], 16, %2;\n"
               :: "r"(dst), "l"(src), "r"(sz) : "memory");
}
__device__ __forceinline__ void cp_commit() { asm volatile("cp.async.commit_group;" ::: "memory"); }
template <int N>
__device__ __forceinline__ void cp_wait() { asm volatile("cp.async.wait_group %0;" :: "n"(N) : "memory"); }
__device__ __forceinline__ float sigf(float x) { return 1.0f / (1.0f + expf(-x)); }
__device__ __forceinline__ void split_bf16(float x, __nv_bfloat16* hi, __nv_bfloat16* lo) {
  __nv_bfloat16 h = __float2bfloat16(x);
  *hi = h;
  *lo = __float2bfloat16(x - __bfloat162float(h));
}

struct GArg {
  const __nv_bfloat16 *Ahi, *Alo;  // [M][K] stride lda
  const __nv_bfloat16 *Whi, *Wlo;  // [N][K] packed
  const float *bias;
  const float *Cadd;
  float *C;
};

#define GS 197632u    // gemm3: 1024 + 3*65536 ; gemm_dec: 1024 + 4*49152

#if USE_TC
// =====================================================================
// tcgen05 path (sm_103a cubin — the one the driver selects)
// =====================================================================
__device__ __forceinline__ uint32_t elect_one_pred() {
  uint32_t pred;
  asm volatile(
      "{\n\t.reg .pred p;\n\telect.sync _|p, 0xFFFFFFFF;\n\tselp.b32 %0, 1, 0, p;\n\t}"
      : "=r"(pred));
  return pred;
}
#define MBARRIER_INIT(addr, cnt) \
  asm volatile("mbarrier.init.shared.b64 [%0], %1;" :: "r"((uint32_t)(addr)), "r"((uint32_t)(cnt)) : "memory")
#define MBARRIER_WAIT_PARITY(addr, par) do {                                        \
  uint32_t _m = (uint32_t)(addr); uint32_t _p = (uint32_t)(par);                    \
  asm volatile("{\n\t.reg .pred P1;\n\t"                                            \
    "WL_%=:\n\t"                                                                    \
    "mbarrier.try_wait.parity.acquire.cta.shared::cta.b64 P1, [%0], %1, 0x989680;\n\t" \
    "@P1 bra.uni WD_%=;\n\t"                                                        \
    "bra.uni WL_%=;\n\t"                                                            \
    "WD_%=:\n\t}" :: "r"(_m), "r"(_p) : "memory");                                  \
} while (0)

#define TCGEN05_ALLOC(sm, n) \
  asm volatile("tcgen05.alloc.cta_group::1.sync.aligned.shared::cta.b32 [%0], %1;" \
               :: "r"((uint32_t)(sm)), "r"((uint32_t)(n)) : "memory")
#define TCGEN05_DEALLOC(t, n) \
  asm volatile("tcgen05.dealloc.cta_group::1.sync.aligned.b32 %0, %1;" :: "r"(t), "r"((uint32_t)(n)))
#define TCGEN05_RELINQ() \
  asm volatile("tcgen05.relinquish_alloc_permit.cta_group::1.sync.aligned;")
#define TCGEN05_COMMIT(mb) \
  asm volatile("tcgen05.commit.cta_group::1.mbarrier::arrive::one.shared::cluster.b64 [%0];" \
               :: "r"((uint32_t)(mb)) : "memory")
#define TCGEN05_FENCE_AFTER()  asm volatile("tcgen05.fence::after_thread_sync;" ::: "memory")
#define TCGEN05_FENCE_BEFORE() asm volatile("tcgen05.fence::before_thread_sync;" ::: "memory")
#define TCGEN05_WAIT_LD()      asm volatile("tcgen05.wait::ld.sync.aligned;" ::: "memory")
#define TCGEN05_LD_32X32B_X32(r, addr)                                            \
  asm volatile(                                                                   \
      "tcgen05.ld.sync.aligned.32x32b.x32.b32 "                                   \
      "{%0, %1, %2, %3, %4, %5, %6, %7, %8, %9, %10, %11, %12, %13, %14, %15, "   \
      " %16, %17, %18, %19, %20, %21, %22, %23, %24, %25, %26, %27, %28, %29, %30, %31}, [%32];" \
      : "=r"((r)[0]), "=r"((r)[1]), "=r"((r)[2]), "=r"((r)[3]),                   \
        "=r"((r)[4]), "=r"((r)[5]), "=r"((r)[6]), "=r"((r)[7]),                   \
        "=r"((r)[8]), "=r"((r)[9]), "=r"((r)[10]), "=r"((r)[11]),                 \
        "=r"((r)[12]), "=r"((r)[13]), "=r"((r)[14]), "=r"((r)[15]),               \
        "=r"((r)[16]), "=r"((r)[17]), "=r"((r)[18]), "=r"((r)[19]),               \
        "=r"((r)[20]), "=r"((r)[21]), "=r"((r)[22]), "=r"((r)[23]),               \
        "=r"((r)[24]), "=r"((r)[25]), "=r"((r)[26]), "=r"((r)[27]),               \
        "=r"((r)[28]), "=r"((r)[29]), "=r"((r)[30]), "=r"((r)[31])                \
      : "r"(addr))

static constexpr unsigned long long SMEM_DESC_BASE_SW128 =
    (2ull << 61) | (1ull << 46) | (64ull << 32) | (1ull << 16);
#define MAKE_SMEM_DESC(a) (SMEM_DESC_BASE_SW128 | ((unsigned long long)((a) >> 4) & 0x3FFF))
static constexpr unsigned long long SMEM_DESC_BASE_SW64 =
    (4ull << 61) | (1ull << 46) | (32ull << 32) | (1ull << 16);
#define MAKE_SMEM_DESC64(a) (SMEM_DESC_BASE_SW64 | ((unsigned long long)((a) >> 4) & 0x3FFF))

template <int TN>
__device__ __forceinline__ void mma_cg1(uint32_t d, unsigned long long a,
                                        unsigned long long b, uint32_t en) {
  constexpr uint32_t idesc =
      (1u << 4) | (1u << 7) | (1u << 10) | ((TN / 8u) << 17) | (8u << 24);
  asm volatile(
      "{\n\t.reg .pred p;\n\tsetp.ne.u32 p, %4, 0;\n\t"
      "tcgen05.mma.cta_group::1.kind::f16 [%0], %1, %2, %3, {%5, %5, %5, %5}, p;\n\t}"
      :: "r"(d), "l"(a), "l"(b), "r"(idesc), "r"(en), "r"(0u) : "memory");
}

// ---------- SW128 stage (KC=64): Ahi@0(16K), Alo@16K, Bhi@32K, Blo after ----
template <int BROWS>
__device__ __forceinline__ void load_stage(
    uint32_t sbase, uint32_t stb, int stage, int ci,
    const __nv_bfloat16* Ahi, const __nv_bfloat16* Alo,
    const __nv_bfloat16* Whi, const __nv_bfloat16* Wlo,
    size_t lda, int m0, int n0, int N, int K, int tid)
{
  const uint32_t base = sbase + (uint32_t)stage * stb;
  const int k0 = ci << 6;
#pragma unroll
  for (int it = 0; it < 4; ++it) {
    int idx = tid + (it << 8);
    int row = idx >> 3, c = idx & 7;
    uint32_t off = (uint32_t)((row << 7) + (c << 4));
    off ^= ((off >> 3) & 0x70);
    size_t so = (size_t)(m0 + row) * lda + (size_t)k0 + (c << 3);
    cp16(base + off, Ahi + so, true);
    cp16(base + 16384u + off, Alo + so, true);
  }
#pragma unroll
  for (int it = 0; it < BROWS / 32; ++it) {
    int idx = tid + (it << 8);
    int row = idx >> 3, c = idx & 7;
    int n = n0 + row;
    bool ok = (n < N);
    size_t so = (size_t)(ok ? n : 0) * (size_t)K + (size_t)k0 + (c << 3);
    uint32_t off = (uint32_t)((row << 7) + (c << 4));
    off ^= ((off >> 3) & 0x70);
    cp16(base + 32768u + off, Whi + so, ok);
    cp16(base + 32768u + (uint32_t)BROWS * 128u + off, Wlo + so, ok);
  }
  cp_commit();
}

template <int TN, int BROWS>
__device__ __forceinline__ void mma_chunk(uint32_t sbase, uint32_t stb,
                                          int stage, uint32_t tmem, bool first) {
  uint32_t base = sbase + (uint32_t)stage * stb;
  unsigned long long dAh = MAKE_SMEM_DESC(base);
  unsigned long long dAl = MAKE_SMEM_DESC(base + 16384u);
  unsigned long long dBh = MAKE_SMEM_DESC(base + 32768u);
  unsigned long long dBl = MAKE_SMEM_DESC(base + 32768u + (uint32_t)BROWS * 128u);
#pragma unroll
  for (int ks = 0; ks < 4; ++ks) {
    unsigned long long o = (unsigned long long)(2 * ks);
    mma_cg1<TN>(tmem, dAh + o, dBh + o, (first && ks == 0) ? 0u : 1u);
    mma_cg1<TN>(tmem, dAh + o, dBl + o, 1u);
    mma_cg1<TN>(tmem, dAl + o, dBh + o, 1u);
  }
}

// ---------------- cg1 GEMM: 128 x TN tiles, S-stage (KC=64) ----------------
template <int TN, int S>
__global__ void __launch_bounds__(256, 1) gemm3(GArg a0, GArg a1, size_t lda,
                                                size_t ldc, int N, int K) {
  extern __shared__ __align__(1024) char smem[];
  const int tid = threadIdx.x;
  const uint32_t sb = smem_u32(smem);
  const GArg g = blockIdx.z ? a1 : a0;
  const int m0 = blockIdx.y * 128;
  const int n0 = blockIdx.x * TN;
  const uint32_t stb = 32768u + (uint32_t)TN * 256u;

  if (tid == 0)
    for (int s = 0; s < S; ++s) MBARRIER_INIT(sb + 16 + 8 * s, 1);
  if (tid < 32) TCGEN05_ALLOC(sb, TN);
  __syncthreads();
  uint32_t tmem;
  asm volatile("ld.shared.b32 %0, [%1];" : "=r"(tmem) : "r"(sb));

  const int nch = K >> 6;
  for (int j = 0; j < S; ++j) {
    if (j < nch) load_stage<TN>(sb + 1024u, stb, j, j, g.Ahi, g.Alo, g.Whi, g.Wlo,
                                lda, m0, n0, N, K, tid);
    else cp_commit();
  }
  for (int i = 0; i < nch; ++i) {
    const int s = i % S;
    if (i >= 1) {
      int pc = i - 1, nc = pc + S;
      if (nc < nch) {
        MBARRIER_WAIT_PARITY(sb + 16 + 8 * (pc % S), (pc / S) & 1);
        load_stage<TN>(sb + 1024u, stb, pc % S, nc, g.Ahi, g.Alo, g.Whi, g.Wlo,
                       lda, m0, n0, N, K, tid);
      } else cp_commit();
    }
    cp_wait<S - 1>();
    asm volatile("fence.proxy.async.shared::cta;" ::: "memory");
    __syncthreads();
    if (tid < 32 && elect_one_pred()) {
      mma_chunk<TN, TN>(sb + 1024u, stb, s, tmem, i == 0);
      TCGEN05_COMMIT(sb + 16 + 8 * s);
    }
  }
  MBARRIER_WAIT_PARITY(sb + 16 + 8 * ((nch - 1) % S), ((nch - 1) / S) & 1);
  TCGEN05_FENCE_AFTER();

  {
    const int wq = (tid >> 5) & 3, wg = tid >> 7, lane = tid & 31;
    const size_t m = (size_t)m0 + (size_t)(wq * 32 + lane);
    float* crow = g.C + m * ldc;
    const float* arow = g.Cadd ? (g.Cadd + m * ldc) : (const float*)0;
    for (int c0 = wg * (TN / 2); c0 < (wg + 1) * (TN / 2); c0 += 32) {
      int n = n0 + c0;
      if (n >= N) break;
      uint32_t r[32];
      TCGEN05_LD_32X32B_X32(r, tmem + c0);
      TCGEN05_WAIT_LD();
      if (((ldc & 3) == 0) && (n + 32 <= N)) {
#pragma unroll
        for (int q = 0; q < 8; ++q) {
          float4 v;
          v.x = __uint_as_float(r[4 * q + 0]);
          v.y = __uint_as_float(r[4 * q + 1]);
          v.z = __uint_as_float(r[4 * q + 2]);
          v.w = __uint_as_float(r[4 * q + 3]);
          if (g.bias) {
            float4 bv = *(const float4*)(g.bias + n + 4 * q);
            v.x += bv.x; v.y += bv.y; v.z += bv.z; v.w += bv.w;
          }
          if (arow) {
            float4 av = *(const float4*)(arow + n + 4 * q);
            v.x += av.x; v.y += av.y; v.z += av.z; v.w += av.w;
          }
          *(float4*)(crow + n + 4 * q) = v;
        }
      } else {
        for (int j = 0; j < 32 && n + j < N; ++j) {
          float v = __uint_as_float(r[j]);
          if (g.bias) v += g.bias[n + j];
          if (arow) v += arow[n + j];
          crow[n + j] = v;
        }
      }
    }
    TCGEN05_FENCE_BEFORE();
  }
  __syncthreads();
  if (tid < 32) { TCGEN05_RELINQ(); TCGEN05_DEALLOC(tmem, TN); }
}

// ---------------- decoder GEMM: 128x256 tiles, KC=32/SW64, 4-stage ----------
#define DSTB 49152u

__device__ __forceinline__ void load_stage_dec(
    uint32_t sbase, int stage, int ci,
    const __nv_bfloat16* Ahi, const __nv_bfloat16* Alo,
    const __nv_bfloat16* Whi, const __nv_bfloat16* Wlo,
    size_t lda, int m0, int n0, int tid)
{
  const uint32_t base = sbase + (uint32_t)stage * DSTB;
  const int k0 = ci << 5;
#pragma unroll
  for (int it = 0; it < 2; ++it) {  // A: 128 rows x 4 chunks(16B) = 512 items
    int idx = tid + (it << 8);
    int row = idx >> 2, c = idx & 3;
    uint32_t off = (uint32_t)((row << 6) + (c << 4));
    off ^= ((off >> 3) & 0x30);
    size_t so = (size_t)(m0 + row) * lda + (size_t)k0 + (c << 3);
    cp16(base + off, Ahi + so, true);
    cp16(base + 8192u + off, Alo + so, true);
  }
#pragma unroll
  for (int it = 0; it < 4; ++it) {  // B: 256 rows x 4 chunks = 1024 items
    int idx = tid + (it << 8);
    int row = idx >> 2, c = idx & 3;
    uint32_t off = (uint32_t)((row << 6) + (c << 4));
    off ^= ((off >> 3) & 0x30);
    size_t so = (size_t)(n0 + row) * (size_t)NHD + (size_t)k0 + (c << 3);
    cp16(base + 16384u + off, Whi + so, true);
    cp16(base + 32768u + off, Wlo + so, true);
  }
  cp_commit();
}

__device__ __forceinline__ void mma_chunk_dec(uint32_t sbase, int stage,
                                              uint32_t tmem, bool first) {
  uint32_t base = sbase + (uint32_t)stage * DSTB;
  unsigned long long dAh = MAKE_SMEM_DESC64(base);
  unsigned long long dAl = MAKE_SMEM_DESC64(base + 8192u);
  unsigned long long dBh = MAKE_SMEM_DESC64(base + 16384u);
  unsigned long long dBl = MAKE_SMEM_DESC64(base + 32768u);
#pragma unroll
  for (int ks = 0; ks < 2; ++ks) {
    unsigned long long o = (unsigned long long)(2 * ks);
    mma_cg1<256>(tmem, dAh + o, dBh + o, (first && ks == 0) ? 0u : 1u);
    mma_cg1<256>(tmem, dAh + o, dBl + o, 1u);
    mma_cg1<256>(tmem, dAl + o, dBh + o, 1u);
  }
}

__global__ void __launch_bounds__(256, 1)
gemm_dec(const __nv_bfloat16* Ahi, const __nv_bfloat16* Alo, size_t lda,
         const __nv_bfloat16* Whi, const __nv_bfloat16* Wlo,
         const float* zp, float* G) {
  extern __shared__ __align__(1024) char smem[];
  const int tid = threadIdx.x;
  const uint32_t sb = smem_u32(smem);
  const int n0 = (int)blockIdx.x * 256;
  const int m0 = (int)blockIdx.y * 128;
  const int nch = NHD >> 5;  // 64

  if (tid == 0)
    for (int s = 0; s < 4; ++s) MBARRIER_INIT(sb + 16 + 8 * s, 1);
  if (tid < 32) TCGEN05_ALLOC(sb, 256);
  __syncthreads();
  uint32_t tmem;
  asm volatile("ld.shared.b32 %0, [%1];" : "=r"(tmem) : "r"(sb));

  load_stage_dec(sb + 1024u, 0, 0, Ahi, Alo, Whi, Wlo, lda, m0, n0, tid);
  load_stage_dec(sb + 1024u, 1, 1, Ahi, Alo, Whi, Wlo, lda, m0, n0, tid);
  load_stage_dec(sb + 1024u, 2, 2, Ahi, Alo, Whi, Wlo, lda, m0, n0, tid);

  for (int i = 0; i < nch; ++i) {
    const int s = i & 3;
    if (i >= 1) {                      // issue load for chunk i+2 (delayed)
      int nc = i + 2;
      if (nc < nch) {
        if (nc >= 4) MBARRIER_WAIT_PARITY(sb + 16 + 8 * (nc & 3), ((nc - 4) >> 2) & 1);
        load_stage_dec(sb + 1024u, nc & 3, nc, Ahi, Alo, Whi, Wlo, lda, m0, n0, tid);
      } else cp_commit();
    }
    cp_wait<2>();
    asm volatile("fence.proxy.async.shared::cta;" ::: "memory");
    __syncthreads();
    if (tid < 32 && elect_one_pred()) {
      mma_chunk_dec(sb + 1024u, s, tmem, i == 0);
      TCGEN05_COMMIT(sb + 16 + 8 * s);
    }
  }
  MBARRIER_WAIT_PARITY(sb + 16 + 8 * ((nch - 1) & 3), ((nch - 1) >> 2) & 1);
  TCGEN05_FENCE_AFTER();

  {
    const int wq = (tid >> 5) & 3, wg = tid >> 7, lane = tid & 31;
    const size_t m = (size_t)m0 + (size_t)(wq * 32 + lane);
    float* crow = G + m * NGD;
    const float* arow = zp + m * NGD;
    for (int c0 = wg * 128; c0 < wg * 128 + 128; c0 += 32) {
      int n = n0 + c0;
      uint32_t r[32];
      TCGEN05_LD_32X32B_X32(r, tmem + c0);
      TCGEN05_WAIT_LD();
#pragma unroll
      for (int q = 0; q < 8; ++q) {
        float4 v;
        v.x = __uint_as_float(r[4 * q + 0]);
        v.y = __uint_as_float(r[4 * q + 1]);
        v.z = __uint_as_float(r[4 * q + 2]);
        v.w = __uint_as_float(r[4 * q + 3]);
        float4 av = *(const float4*)(arow + n + 4 * q);
        v.x += av.x; v.y += av.y; v.z += av.z; v.w += av.w;
        *(float4*)(crow + n + 4 * q) = v;
      }
    }
    TCGEN05_FENCE_BEFORE();
  }
  __syncthreads();
  if (tid < 32) { TCGEN05_RELINQ(); TCGEN05_DEALLOC(tmem, 256); }
}

#else
// =====================================================================
// Naive fallback (sm_103 non-a pass; never selected at runtime)
// =====================================================================
template <int TN, int S>
__global__ void __launch_bounds__(256, 1) gemm3(GArg a0, GArg a1, size_t lda,
                                                size_t ldc, int N, int K) {
  const GArg g = blockIdx.z ? a1 : a0;
  int m0 = blockIdx.y * 128, n0 = blockIdx.x * TN;
  for (int e = threadIdx.x; e < 128 * TN; e += 256) {
    int m = m0 + e / TN, n = n0 + e % TN;
    if (n >= N) continue;
    float s = 0.f;
    const __nv_bfloat16 *ah = g.Ahi + (size_t)m * lda, *al = g.Alo + (size_t)m * lda;
    const __nv_bfloat16 *wh = g.Whi + (size_t)n * K, *wl = g.Wlo + (size_t)n * K;
    for (int k = 0; k < K; ++k)
      s += (__bfloat162float(ah[k]) + __bfloat162float(al[k])) *
           (__bfloat162float(wh[k]) + __bfloat162float(wl[k]));
    if (g.bias) s += g.bias[n];
    if (g.Cadd) s += g.Cadd[(size_t)m * ldc + n];
    g.C[(size_t)m * ldc + n] = s;
  }
}
__global__ void __launch_bounds__(256, 1) gemm_dec(
    const __nv_bfloat16* Ahi, const __nv_bfloat16* Alo, size_t lda,
    const __nv_bfloat16* Whi, const __nv_bfloat16* Wlo,
    const float* zp, float* G) {
  int m0 = blockIdx.y * 128, n0 = blockIdx.x * 256;
  for (int e = threadIdx.x; e < 128 * 256; e += 256) {
    int m = m0 + e / 256, n = n0 + e % 256;
    float s = 0.f;
    const __nv_bfloat16 *ah = Ahi + (size_t)m * lda, *al = Alo + (size_t)m * lda;
    const __nv_bfloat16 *wh = Whi + (size_t)n * NHD, *wl = Wlo + (size_t)n * NHD;
    for (int k = 0; k < NHD; ++k)
      s += (__bfloat162float(ah[k]) + __bfloat162float(al[k])) *
           (__bfloat162float(wh[k]) + __bfloat162float(wl[k]));
    G[(size_t)m * NGD + n] = s + zp[(size_t)m * NGD + n];
  }
}
#endif  // USE_TC

// ---------------- cvt_all ----------------
#define SEG0 16777216L
#define SEG1 (SEG0 + 1048576L)
#define SEG2 (SEG1 + 1048576L)
#define SEG3 (SEG2 + 262144L)
#define SEG4 (SEG3 + 524288L)
#define SEG5 (SEG4 + 1048576L)
#define SEG6 (SEG5 + 251904L)
#define SEG7 (SEG6 + 524288L)
#define SEG8 (SEG7 + 8192L)
__global__ void cvt_all(const float* __restrict__ dWhh, const float* __restrict__ eWf,
                        const float* __restrict__ eWb, const float* __restrict__ eOut,
                        const float* __restrict__ initW, const float* __restrict__ decWih,
                        const float* __restrict__ outW) {
  long idx = blockIdx.x * 256L + threadIdx.x;
  if (idx >= SEG8) return;
  if (idx < SEG0) {
    split_bf16(dWhh[idx], &g_dWhh_hi[idx], &g_dWhh_lo[idx]);
  } else if (idx < SEG1) {
    long i = idx - SEG0; split_bf16(eWf[i], &g_eWf_hi[i], &g_eWf_lo[i]);
  } else if (idx < SEG2) {
    long i = idx - SEG1; split_bf16(eWb[i], &g_eWb_hi[i], &g_eWb_lo[i]);
  } else if (idx < SEG3) {
    long i = idx - SEG2; split_bf16(eOut[i], &g_eOut_hi[i], &g_eOut_lo[i]);
  } else if (idx < SEG4) {
    long i = idx - SEG3; split_bf16(initW[i], &g_initW_hi[i], &g_initW_lo[i]);
  } else if (idx < SEG5) {
    long i = idx - SEG4;
    long n = i >> 7, k = i & 127;
    split_bf16(decWih[n * DLD + 5 + k], &g_zW_hi[i], &g_zW_lo[i]);
  } else if (idx < SEG6) {
    long i = idx - SEG5; split_bf16(outW[i], &g_outW_hi[i], &g_outW_lo[i]);
  } else if (idx < SEG7) {
    long i = idx - SEG6;
    g_hn_hi[i] = __float2bfloat16(0.0f);
    g_hn_lo[i] = __float2bfloat16(0.0f);
    g_ce[i] = 0.0f;
  } else {
    int r = (int)(idx - SEG7);
    g_dWih2[r] = make_float2(decWih[(long)r * DLD], decWih[(long)r * DLD + 1]);
  }
}

// ---------------- gate / small kernels ----------------
__global__ void enc_gate_kernel(const float* __restrict__ data,
                                const int* __restrict__ lengths,
                                const float* __restrict__ Wih_f,
                                const float* __restrict__ Wih_b, int t) {
  int idx = blockIdx.x * blockDim.x + threadIdx.x;
  int dir = idx >> 18;
  int rr = idx & ((1 << 18) - 1);
  int b = rr >> 9;
  int j = rr & 511;
  int L = lengths[b];
  L = L < 1 ? 1 : (L > NT ? NT : L);
  if (t >= L) return;
  int ti = dir ? (L - 1 - t) : t;
  float x0 = data[((size_t)b * DATALD + ti + 1) * 2 + 0];
  float x1 = data[((size_t)b * DATALD + ti + 1) * 2 + 1];
  const float* Wih = dir ? Wih_b : Wih_f;
  const float* G = g_Ge + (size_t)(dir * NB + b) * NGE;
  float pi = G[j]           + x0 * Wih[2 * j]               + x1 * Wih[2 * j + 1];
  float pf = G[NHE + j]     + x0 * Wih[2 * (NHE + j)]       + x1 * Wih[2 * (NHE + j) + 1];
  float pg = G[2 * NHE + j] + x0 * Wih[2 * (2 * NHE + j)]   + x1 * Wih[2 * (2 * NHE + j) + 1];
  float po = G[3 * NHE + j] + x0 * Wih[2 * (3 * NHE + j)]   + x1 * Wih[2 * (3 * NHE + j) + 1];
  int ci = (dir * NB + b) * NHE + j;
  float c = g_ce[ci];
  float c2 = sigf(pf) * c + sigf(pi) * tanhf(pg);
  float h2 = sigf(po) * tanhf(c2);
  g_ce[ci] = c2;
  int hidx = b * (2 * NHE) + dir * NHE + j;
  split_bf16(h2, &g_hn_hi[hidx], &g_hn_lo[hidx]);
}

__global__ void latent_kernel(const float* __restrict__ eps,
                              float* __restrict__ zm_out,
                              float* __restrict__ zl_out) {
  int idx = blockIdx.x * blockDim.x + threadIdx.x;
  int b = idx >> 7, k = idx & 127;
  float zm = g_zml[b * 256 + k];
  float zl = g_zml[b * 256 + 128 + k];
  zm_out[idx] = zm;
  zl_out[idx] = zl;
  float z = zm + expf(0.5f * zl) * eps[idx];
  split_bf16(z, &g_z_hi[idx], &g_z_lo[idx]);
}

__global__ void initsplit_kernel() {
  int idx = blockIdx.x * blockDim.x + threadIdx.x;
  int b = idx >> 11, j = idx & 2047;
  float h0 = tanhf(g_init[b * (2 * NHD) + j]);
  float c0 = tanhf(g_init[b * (2 * NHD) + NHD + j]);
  g_cd[idx] = c0;
  split_bf16(h0, &g_h0_hi[idx], &g_h0_lo[idx]);
}

__global__ void dec_gate_kernel(const float* __restrict__ data, int t) {
  int idx = blockIdx.x * blockDim.x + threadIdx.x;
  int b = idx >> 11, j = idx & 2047;
  float x0 = data[((size_t)b * DATALD + t) * 2 + 0];
  float x1 = data[((size_t)b * DATALD + t) * 2 + 1];
  const float* G = g_G + (size_t)b * NGD;
  int r0 = j, r1 = j + NHD, r2 = j + 2 * NHD, r3 = j + 3 * NHD;
  float2 w0 = g_dWih2[r0], w1 = g_dWih2[r1], w2 = g_dWih2[r2], w3 = g_dWih2[r3];
  float pi = G[r0] + x0 * w0.x + x1 * w0.y;
  float pf = G[r1] + x0 * w1.x + x1 * w1.y;
  float pg = G[r2] + x0 * w2.x + x1 * w2.y;
  float po = G[r3] + x0 * w3.x + x1 * w3.y;
  float c = g_cd[idx];
  float c2 = sigf(pf) * c + sigf(pi) * tanhf(pg);
  float h2 = sigf(po) * tanhf(c2);
  g_cd[idx] = c2;
  size_t ho = ((size_t)b * NT + t) * NHD + j;
  split_bf16(h2, &g_hs_hi[ho], &g_hs_lo[ho]);
}

// ---------------- launch ----------------
static inline void run_gemm(const GArg& a0, const GArg& a1, size_t lda, size_t ldc,
                            int N, int K, int M, int nz) {
  dim3 grid((unsigned)((N + 127) / 128), (unsigned)(M / 128), (unsigned)nz);
  gemm3<128, 3><<<grid, 256, GS>>>(a0, a1, lda, ldc, N, K);
}

extern "C" void kernel_launch(void* const* d_in, const int* in_sizes, int n_in,
                              void* d_out, int out_size) {
  const float* data      = (const float*)d_in[0];
  const float* eps       = (const float*)d_in[1];
  const float* enc_Wih_f = (const float*)d_in[2];
  const float* enc_Whh_f = (const float*)d_in[3];
  const float* enc_b_f   = (const float*)d_in[4];
  const float* enc_Wih_b = (const float*)d_in[5];
  const float* enc_Whh_b = (const float*)d_in[6];
  const float* enc_b_b   = (const float*)d_in[7];
  const float* enc_out_W = (const float*)d_in[8];
  const float* enc_out_b = (const float*)d_in[9];
  const float* init_W    = (const float*)d_in[10];
  const float* init_b    = (const float*)d_in[11];
  const float* dec_Wih   = (const float*)d_in[12];
  const float* dec_Whh   = (const float*)d_in[13];
  const float* dec_b     = (const float*)d_in[14];
  const float* out_W     = (const float*)d_in[15];
  const float* out_b     = (const float*)d_in[16];
  const int*   lengths   = (const int*)d_in[17];

  float* out    = (float*)d_out;
  float* params = out;
  float* zm_out = out + (size_t)NB * NT * NOUTD;
  float* zl_out = zm_out + (size_t)NB * NT;

  cudaFuncSetAttribute(gemm3<128, 3>, cudaFuncAttributeMaxDynamicSharedMemorySize, GS);
  cudaFuncSetAttribute(gemm_dec, cudaFuncAttributeMaxDynamicSharedMemorySize, GS);

#define SYM(p, s) cudaGetSymbolAddress((void**)&p, s)
  __nv_bfloat16 *dWhh_hi, *dWhh_lo, *eWf_hi, *eWf_lo, *eWb_hi, *eWb_lo;
  __nv_bfloat16 *eOut_hi, *eOut_lo, *initW_hi, *initW_lo, *zW_hi, *zW_lo, *outW_hi, *outW_lo;
  __nv_bfloat16 *hn_hi, *hn_lo, *z_hi, *z_lo, *h0_hi, *h0_lo, *hs_hi, *hs_lo;
  float *Ge, *zml, *initb, *zp, *G;
  SYM(dWhh_hi, g_dWhh_hi); SYM(dWhh_lo, g_dWhh_lo);
  SYM(eWf_hi, g_eWf_hi); SYM(eWf_lo, g_eWf_lo);
  SYM(eWb_hi, g_eWb_hi); SYM(eWb_lo, g_eWb_lo);
  SYM(eOut_hi, g_eOut_hi); SYM(eOut_lo, g_eOut_lo);
  SYM(initW_hi, g_initW_hi); SYM(initW_lo, g_initW_lo);
  SYM(zW_hi, g_zW_hi); SYM(zW_lo, g_zW_lo);
  SYM(outW_hi, g_outW_hi); SYM(outW_lo, g_outW_lo);
  SYM(hn_hi, g_hn_hi); SYM(hn_lo, g_hn_lo);
  SYM(z_hi, g_z_hi); SYM(z_lo, g_z_lo);
  SYM(h0_hi, g_h0_hi); SYM(h0_lo, g_h0_lo);
  SYM(hs_hi, g_hs_hi); SYM(hs_lo, g_hs_lo);
  SYM(Ge, g_Ge); SYM(zml, g_zml); SYM(initb, g_init); SYM(zp, g_zp); SYM(G, g_G);
#undef SYM

  cvt_all<<<(unsigned)((SEG8 + 255) / 256), 256>>>(
      dec_Whh, enc_Whh_f, enc_Whh_b, enc_out_W, init_W, dec_Wih, out_W);

  // ---- bidirectional encoder, 128 steps ----
  for (int t = 0; t < NT; t++) {
    GArg f = {hn_hi, hn_lo, eWf_hi, eWf_lo, enc_b_f, nullptr, Ge};
    GArg bw = {hn_hi + NHE, hn_lo + NHE, eWb_hi, eWb_lo, enc_b_b, nullptr,
               Ge + (size_t)NB * NGE};
    run_gemm(f, bw, 2 * NHE, NGE, NGE, NHE, NB, 2);
    enc_gate_kernel<<<2048, 256>>>(data, lengths, enc_Wih_f, enc_Wih_b, t);
  }

  // ---- latent ----
  {
    GArg a = {hn_hi, hn_lo, eOut_hi, eOut_lo, enc_out_b, nullptr, zml};
    run_gemm(a, a, 2 * NHE, 2 * NZ, 2 * NZ, 2 * NHE, NB, 1);
  }
  latent_kernel<<<256, 256>>>(eps, zm_out, zl_out);
  {
    GArg a = {z_hi, z_lo, initW_hi, initW_lo, init_b, nullptr, initb};
    run_gemm(a, a, NZ, 2 * NHD, 2 * NHD, NZ, NB, 1);
  }
  initsplit_kernel<<<4096, 256>>>();
  {
    GArg a = {z_hi, z_lo, zW_hi, zW_lo, dec_b, nullptr, zp};
    run_gemm(a, a, NZ, NGD, NGD, NZ, NB, 1);
  }

  // ---- decoder, 128 steps (KC=32/SW64 4-stage GEMM + gate) ----
  for (int t = 0; t < NT; t++) {
    const __nv_bfloat16* Ah = t ? (hs_hi + (size_t)(t - 1) * NHD) : h0_hi;
    const __nv_bfloat16* Al = t ? (hs_lo + (size_t)(t - 1) * NHD) : h0_lo;
    size_t lda = t ? (size_t)NT * NHD : (size_t)NHD;
    gemm_dec<<<dim3(32, 4), 256, GS>>>(Ah, Al, lda, dWhh_hi, dWhh_lo, zp, G);
    dec_gate_kernel<<<4096, 256>>>(data, t);
  }

  // ---- output projection ----
  {
    GArg a = {hs_hi, hs_lo, outW_hi, outW_lo, out_b, nullptr, params};
    run_gemm(a, a, NHD, NOUTD, NOUTD, NHD, NB * NT, 1);
  }
}